// round 1
// baseline (speedup 1.0000x reference)
#include <cuda_runtime.h>
#include <math_constants.h>

#define D_MODEL   1024
#define N_HEADS   16
#define HEAD_DIM  64
#define BATCH     2
#define SEQ       2048
#define M_TOT     (BATCH * SEQ)   // 4096

// ---------------------------------------------------------------------------
// Scratch (no cudaMalloc allowed): Q, K, V projections + attention output
// ---------------------------------------------------------------------------
__device__ float g_Q[M_TOT * D_MODEL];
__device__ float g_K[M_TOT * D_MODEL];
__device__ float g_V[M_TOT * D_MODEL];
__device__ float g_att[M_TOT * D_MODEL];

// ---------------------------------------------------------------------------
// SGEMM with bias: Y[m][o] = sum_d X[m][d] * W[o][d] + bias[o]
// (torch Linear: y = x @ W^T + b; both operands K-major / row-major)
// BM=BN=128, BK=8, 256 threads, 8x8 per-thread tile.
// ---------------------------------------------------------------------------
__global__ __launch_bounds__(256) void sgemm_bias_kernel(
    const float* __restrict__ X, const float* __restrict__ W,
    const float* __restrict__ bias, float* __restrict__ Y,
    int M, int N, int K)
{
    constexpr int BM = 128, BN = 128, BK = 8;
    __shared__ float As[BK][BM];
    __shared__ float Bs[BK][BN];

    const int tid  = threadIdx.x;
    const int bm   = blockIdx.y * BM;
    const int bn   = blockIdx.x * BN;
    const int lrow = tid >> 1;          // 0..127
    const int lseg = (tid & 1) * 4;     // 0 or 4
    const int ty   = tid >> 4;          // 0..15
    const int tx   = tid & 15;          // 0..15

    const float* Xp = X + (bm + lrow) * K + lseg;
    const float* Wp = W + (bn + lrow) * K + lseg;

    float acc[8][8];
#pragma unroll
    for (int i = 0; i < 8; i++)
#pragma unroll
        for (int j = 0; j < 8; j++) acc[i][j] = 0.f;

    for (int k0 = 0; k0 < K; k0 += BK) {
        float4 a = *(const float4*)(Xp + k0);
        float4 b = *(const float4*)(Wp + k0);
        As[lseg + 0][lrow] = a.x;
        As[lseg + 1][lrow] = a.y;
        As[lseg + 2][lrow] = a.z;
        As[lseg + 3][lrow] = a.w;
        Bs[lseg + 0][lrow] = b.x;
        Bs[lseg + 1][lrow] = b.y;
        Bs[lseg + 2][lrow] = b.z;
        Bs[lseg + 3][lrow] = b.w;
        __syncthreads();

#pragma unroll
        for (int k = 0; k < BK; k++) {
            float ra[8], rb[8];
            *(float4*)(ra)     = *(const float4*)&As[k][ty * 8];
            *(float4*)(ra + 4) = *(const float4*)&As[k][ty * 8 + 4];
            *(float4*)(rb)     = *(const float4*)&Bs[k][tx * 8];
            *(float4*)(rb + 4) = *(const float4*)&Bs[k][tx * 8 + 4];
#pragma unroll
            for (int i = 0; i < 8; i++)
#pragma unroll
                for (int j = 0; j < 8; j++)
                    acc[i][j] = fmaf(ra[i], rb[j], acc[i][j]);
        }
        __syncthreads();
    }

#pragma unroll
    for (int i = 0; i < 8; i++) {
        const int row = bm + ty * 8 + i;
        const int col = bn + tx * 8;
        float4 o0 = make_float4(acc[i][0] + bias[col + 0], acc[i][1] + bias[col + 1],
                                acc[i][2] + bias[col + 2], acc[i][3] + bias[col + 3]);
        float4 o1 = make_float4(acc[i][4] + bias[col + 4], acc[i][5] + bias[col + 5],
                                acc[i][6] + bias[col + 6], acc[i][7] + bias[col + 7]);
        *(float4*)&Y[(long)row * N + col]     = o0;
        *(float4*)&Y[(long)row * N + col + 4] = o1;
    }
}

// ---------------------------------------------------------------------------
// Flash attention, fp32. One CTA = 64 queries of one (b, h).
// 256 threads in a 16x16 grid, each owns a 4x4 micro-tile of both the
// 64x64 score tile and the 64x64 output tile.
// Shared layouts chosen so all inner-loop LDS are float4 & conflict-free:
//   Qs[d][i], Ks[d][j] (transposed), Vs[j][d] (direct), Ps[j][i] (stride 68).
// ---------------------------------------------------------------------------
#define BQ   64
#define BKV  64
#define PSTR 68
#define ATTN_SMEM_FLOATS (HEAD_DIM*BQ + HEAD_DIM*BKV + BKV*HEAD_DIM + BKV*PSTR + 2*BQ)
#define ATTN_SMEM_BYTES  (ATTN_SMEM_FLOATS * 4)

__global__ __launch_bounds__(256) void flash_attn_kernel(
    const float* __restrict__ Qg, const float* __restrict__ Kg,
    const float* __restrict__ Vg, const int* __restrict__ mask,
    float* __restrict__ Og)
{
    extern __shared__ float sm[];
    float* Qs  = sm;                         // [HD][BQ]
    float* Ks  = Qs + HEAD_DIM * BQ;         // [HD][BKV]
    float* Vs  = Ks + HEAD_DIM * BKV;        // [BKV][HD]
    float* Ps  = Vs + BKV * HEAD_DIM;        // [BKV][PSTR]
    float* m_s = Ps + BKV * PSTR;            // [BQ]
    float* l_s = m_s + BQ;                   // [BQ]

    const int tid = threadIdx.x;
    const int ty  = tid >> 4;      // 0..15
    const int tx  = tid & 15;      // 0..15
    const int i0  = ty * 4;        // q-row base within tile
    const int c0  = tx * 4;        // col base (k-col for S, d-col for O)

    const int qt = blockIdx.x;
    const int h  = blockIdx.y;
    const int b  = blockIdx.z;
    const int qbase = qt * BQ;
    const float scale = 0.125f;    // 1/sqrt(64)

    // ---- load Q tile (transposed into Qs[d][i]) ----
    {
        const int r   = tid >> 2;          // 0..63
        const int seg = (tid & 3) * 16;    // 0,16,32,48
        const float* src = Qg + ((long)(b * SEQ + qbase + r)) * D_MODEL + h * HEAD_DIM + seg;
#pragma unroll
        for (int u = 0; u < 4; u++) {
            float4 v = *(const float4*)(src + 4 * u);
            const int d = seg + 4 * u;
            Qs[(d + 0) * BQ + r] = v.x;
            Qs[(d + 1) * BQ + r] = v.y;
            Qs[(d + 2) * BQ + r] = v.z;
            Qs[(d + 3) * BQ + r] = v.w;
        }
    }
    if (tid < BQ) { m_s[tid] = -CUDART_INF_F; l_s[tid] = 0.f; }

    float acc[4][4];
#pragma unroll
    for (int i = 0; i < 4; i++)
#pragma unroll
        for (int j = 0; j < 4; j++) acc[i][j] = 0.f;

    for (int kt = 0; kt < SEQ; kt += BKV) {
        __syncthreads();   // protect Ks/Vs/Ps reuse from previous iteration

        // ---- load K (transposed) and V (direct) tiles ----
        {
            const int r   = tid >> 2;
            const int seg = (tid & 3) * 16;
            const float* ksrc = Kg + ((long)(b * SEQ + kt + r)) * D_MODEL + h * HEAD_DIM + seg;
            const float* vsrc = Vg + ((long)(b * SEQ + kt + r)) * D_MODEL + h * HEAD_DIM + seg;
#pragma unroll
            for (int u = 0; u < 4; u++) {
                const int d = seg + 4 * u;
                float4 v = *(const float4*)(ksrc + 4 * u);
                Ks[(d + 0) * BKV + r] = v.x;
                Ks[(d + 1) * BKV + r] = v.y;
                Ks[(d + 2) * BKV + r] = v.z;
                Ks[(d + 3) * BKV + r] = v.w;
                float4 w = *(const float4*)(vsrc + 4 * u);
                *(float4*)&Vs[r * HEAD_DIM + d] = w;
            }
        }
        __syncthreads();

        // ---- S = Q K^T (64x64x64) ----
        float s[4][4];
#pragma unroll
        for (int i = 0; i < 4; i++)
#pragma unroll
            for (int j = 0; j < 4; j++) s[i][j] = 0.f;

#pragma unroll 8
        for (int d = 0; d < HEAD_DIM; d++) {
            float4 ra = *(const float4*)&Qs[d * BQ + i0];
            float4 rb = *(const float4*)&Ks[d * BKV + c0];
            float aa[4] = {ra.x, ra.y, ra.z, ra.w};
            float bb[4] = {rb.x, rb.y, rb.z, rb.w};
#pragma unroll
            for (int i = 0; i < 4; i++)
#pragma unroll
                for (int j = 0; j < 4; j++)
                    s[i][j] = fmaf(aa[i], bb[j], s[i][j]);
        }

        // ---- scale + mask ----
#pragma unroll
        for (int ii = 0; ii < 4; ii++) {
            const int q = qbase + i0 + ii;
            const int4 mm = *(const int4*)(mask + ((long)(b * SEQ + q)) * SEQ + kt + c0);
            s[ii][0] = mm.x ? s[ii][0] * scale : -1e30f;
            s[ii][1] = mm.y ? s[ii][1] * scale : -1e30f;
            s[ii][2] = mm.z ? s[ii][2] * scale : -1e30f;
            s[ii][3] = mm.w ? s[ii][3] * scale : -1e30f;
        }

        // ---- online softmax (row reduce over 16 tx lanes via shfl) ----
#pragma unroll
        for (int ii = 0; ii < 4; ii++) {
            float rmax = fmaxf(fmaxf(s[ii][0], s[ii][1]), fmaxf(s[ii][2], s[ii][3]));
            rmax = fmaxf(rmax, __shfl_xor_sync(0xffffffffu, rmax, 1));
            rmax = fmaxf(rmax, __shfl_xor_sync(0xffffffffu, rmax, 2));
            rmax = fmaxf(rmax, __shfl_xor_sync(0xffffffffu, rmax, 4));
            rmax = fmaxf(rmax, __shfl_xor_sync(0xffffffffu, rmax, 8));

            const float m_old = m_s[i0 + ii];
            const float m_new = fmaxf(m_old, rmax);

            float p0 = __expf(s[ii][0] - m_new);
            float p1 = __expf(s[ii][1] - m_new);
            float p2 = __expf(s[ii][2] - m_new);
            float p3 = __expf(s[ii][3] - m_new);
            float rsum = p0 + p1 + p2 + p3;
            rsum += __shfl_xor_sync(0xffffffffu, rsum, 1);
            rsum += __shfl_xor_sync(0xffffffffu, rsum, 2);
            rsum += __shfl_xor_sync(0xffffffffu, rsum, 4);
            rsum += __shfl_xor_sync(0xffffffffu, rsum, 8);

            const float alpha = __expf(m_old - m_new);
            acc[ii][0] *= alpha; acc[ii][1] *= alpha;
            acc[ii][2] *= alpha; acc[ii][3] *= alpha;

            __syncwarp();   // all lanes read m_s/l_s-era state before tx==0 writes
            if (tx == 0) {
                m_s[i0 + ii] = m_new;
                l_s[i0 + ii] = l_s[i0 + ii] * alpha + rsum;
            }

            Ps[(c0 + 0) * PSTR + i0 + ii] = p0;
            Ps[(c0 + 1) * PSTR + i0 + ii] = p1;
            Ps[(c0 + 2) * PSTR + i0 + ii] = p2;
            Ps[(c0 + 3) * PSTR + i0 + ii] = p3;
        }
        __syncthreads();

        // ---- O += P V (64x64x64) ----
#pragma unroll 8
        for (int j = 0; j < BKV; j++) {
            float4 ra = *(const float4*)&Ps[j * PSTR + i0];
            float4 rb = *(const float4*)&Vs[j * HEAD_DIM + c0];
            float aa[4] = {ra.x, ra.y, ra.z, ra.w};
            float bb[4] = {rb.x, rb.y, rb.z, rb.w};
#pragma unroll
            for (int i = 0; i < 4; i++)
#pragma unroll
                for (int jj = 0; jj < 4; jj++)
                    acc[i][jj] = fmaf(aa[i], bb[jj], acc[i][jj]);
        }
    }

    // ---- epilogue: normalize and write (B,T,D) layout ----
#pragma unroll
    for (int ii = 0; ii < 4; ii++) {
        const float inv = 1.0f / l_s[i0 + ii];
        float4 o = make_float4(acc[ii][0] * inv, acc[ii][1] * inv,
                               acc[ii][2] * inv, acc[ii][3] * inv);
        *(float4*)(Og + ((long)(b * SEQ + qbase + i0 + ii)) * D_MODEL + h * HEAD_DIM + c0) = o;
    }
}

// ---------------------------------------------------------------------------
// Launcher
// inputs: query key value mask wq bq wk bk wv bv wo bo
// ---------------------------------------------------------------------------
extern "C" void kernel_launch(void* const* d_in, const int* in_sizes, int n_in,
                              void* d_out, int out_size)
{
    const float* query = (const float*)d_in[0];
    const float* key   = (const float*)d_in[1];
    const float* value = (const float*)d_in[2];
    const int*   mask  = (const int*)  d_in[3];
    const float* wq    = (const float*)d_in[4];
    const float* bq    = (const float*)d_in[5];
    const float* wk    = (const float*)d_in[6];
    const float* bk    = (const float*)d_in[7];
    const float* wv    = (const float*)d_in[8];
    const float* bv    = (const float*)d_in[9];
    const float* wo    = (const float*)d_in[10];
    const float* bo    = (const float*)d_in[11];
    float* out = (float*)d_out;

    float *Qb, *Kb, *Vb, *Ab;
    cudaGetSymbolAddress((void**)&Qb, g_Q);
    cudaGetSymbolAddress((void**)&Kb, g_K);
    cudaGetSymbolAddress((void**)&Vb, g_V);
    cudaGetSymbolAddress((void**)&Ab, g_att);

    dim3 gg(D_MODEL / 128, M_TOT / 128);   // (8, 32)
    sgemm_bias_kernel<<<gg, 256>>>(query, wq, bq, Qb, M_TOT, D_MODEL, D_MODEL);
    sgemm_bias_kernel<<<gg, 256>>>(key,   wk, bk, Kb, M_TOT, D_MODEL, D_MODEL);
    sgemm_bias_kernel<<<gg, 256>>>(value, wv, bv, Vb, M_TOT, D_MODEL, D_MODEL);

    cudaFuncSetAttribute(flash_attn_kernel,
                         cudaFuncAttributeMaxDynamicSharedMemorySize, ATTN_SMEM_BYTES);
    dim3 ga(SEQ / BQ, N_HEADS, BATCH);     // (32, 16, 2)
    flash_attn_kernel<<<ga, 256, ATTN_SMEM_BYTES>>>(Qb, Kb, Vb, mask, Ab);

    sgemm_bias_kernel<<<gg, 256>>>(Ab, wo, bo, out, M_TOT, D_MODEL, D_MODEL);
}

// round 3
// speedup vs baseline: 1.3139x; 1.3139x over previous
#include <cuda_runtime.h>
#include <cuda_bf16.h>
#include <math_constants.h>
#include <cstdint>

#define D_MODEL   1024
#define N_HEADS   16
#define HEAD_DIM  64
#define BATCH     2
#define SEQ       2048
#define M_TOT     (BATCH * SEQ)   // 4096
#define GK        1024

// ---------------------------------------------------------------------------
// Scratch (no cudaMalloc allowed)
// ---------------------------------------------------------------------------
__device__ float g_Q[M_TOT * D_MODEL];
__device__ float g_K[M_TOT * D_MODEL];
__device__ float g_V[M_TOT * D_MODEL];
__device__ float g_att[M_TOT * D_MODEL];

// ---------------------------------------------------------------------------
// Warp-MMA helpers (target-portable: ldmatrix sm_75+, bf16 mma sm_80+)
// ---------------------------------------------------------------------------
__device__ __forceinline__ uint32_t smem_to_u32(const void* smem_ptr) {
    uint32_t addr;
    asm("{ .reg .u64 tmp; cvta.to.shared.u64 tmp, %1; cvt.u32.u64 %0, tmp; }"
        : "=r"(addr) : "l"(smem_ptr));
    return addr;
}

__device__ __forceinline__ void ldmx4(uint32_t* r, uint32_t addr) {
    asm volatile("ldmatrix.sync.aligned.m8n8.x4.shared.b16 {%0,%1,%2,%3}, [%4];"
        : "=r"(r[0]), "=r"(r[1]), "=r"(r[2]), "=r"(r[3]) : "r"(addr));
}
__device__ __forceinline__ void ldmx2(uint32_t* r, uint32_t addr) {
    asm volatile("ldmatrix.sync.aligned.m8n8.x2.shared.b16 {%0,%1}, [%2];"
        : "=r"(r[0]), "=r"(r[1]) : "r"(addr));
}

__device__ __forceinline__ void mma_bf16(float* d, const uint32_t* a, const uint32_t* b) {
    asm volatile(
        "mma.sync.aligned.m16n8k16.row.col.f32.bf16.bf16.f32 "
        "{%0,%1,%2,%3}, {%4,%5,%6,%7}, {%8,%9}, {%0,%1,%2,%3};"
        : "+f"(d[0]), "+f"(d[1]), "+f"(d[2]), "+f"(d[3])
        : "r"(a[0]), "r"(a[1]), "r"(a[2]), "r"(a[3]), "r"(b[0]), "r"(b[1]));
}

// ---------------------------------------------------------------------------
// Split-bf16 HMMA GEMM:  Y[m][o] = sum_d X[m][d] * W[o][d] + bias[o]
// CTA tile 128x128, BK=32, 8 warps (2x4), warp tile 64x32 (4x4 m16n8k16).
// D = Ah*Bh + Ah*Bl + Al*Bh  (fp32 accum; drops only Al*Bl ~ 1e-5 rel)
// ---------------------------------------------------------------------------
#define GSTR 40                      // smem halves per row (32 + 8 pad)
#define GROW (GSTR * 2)              // bytes per row

__global__ __launch_bounds__(256) void gemm_mma_kernel(
    const float* __restrict__ X, const float* __restrict__ W,
    const float* __restrict__ bias, float* __restrict__ Y)
{
    __shared__ __align__(16) __nv_bfloat16 Ah[128 * GSTR], Al[128 * GSTR];
    __shared__ __align__(16) __nv_bfloat16 Bh[128 * GSTR], Bl[128 * GSTR];

    const int tid    = threadIdx.x;
    const int wid    = tid >> 5;
    const int lane   = tid & 31;
    const int warp_m = wid & 1;       // 0..1 -> 64 rows each
    const int warp_n = wid >> 1;      // 0..3 -> 32 cols each
    const int bm = blockIdx.y * 128;
    const int bn = blockIdx.x * 128;

    float acc[4][4][4];
#pragma unroll
    for (int i = 0; i < 4; i++)
#pragma unroll
        for (int j = 0; j < 4; j++)
#pragma unroll
            for (int k = 0; k < 4; k++) acc[i][j][k] = 0.f;

    // global load mapping: each thread loads 16 floats of A and 16 of B per chunk
    const int lrow = tid >> 1;          // 0..127
    const int lseg = (tid & 1) * 16;    // 0 or 16
    const float* Xp = X + (size_t)(bm + lrow) * GK + lseg;
    const float* Wp = W + (size_t)(bn + lrow) * GK + lseg;

    const uint32_t AhB = smem_to_u32(Ah), AlB = smem_to_u32(Al);
    const uint32_t BhB = smem_to_u32(Bh), BlB = smem_to_u32(Bl);

    // ldmatrix per-lane offsets (bytes)
    const uint32_t a_off = ((uint32_t)(lane & 15) * GSTR + (uint32_t)(lane >> 4) * 8) * 2
                         + (uint32_t)(warp_m * 64) * GROW;
    const uint32_t b_off = ((uint32_t)(lane & 7) * GSTR + (uint32_t)((lane >> 3) & 1) * 8) * 2
                         + (uint32_t)(warp_n * 32) * GROW;

    __nv_bfloat16* AhS = Ah + lrow * GSTR + lseg;
    __nv_bfloat16* AlS = Al + lrow * GSTR + lseg;
    __nv_bfloat16* BhS = Bh + lrow * GSTR + lseg;
    __nv_bfloat16* BlS = Bl + lrow * GSTR + lseg;

    for (int kc = 0; kc < GK; kc += 32) {
        // ---- load fp32, split to bf16 hi/lo, store to smem ----
        {
            float fa[16], fb[16];
#pragma unroll
            for (int u = 0; u < 4; u++) {
                *(float4*)(fa + 4 * u) = *(const float4*)(Xp + kc + 4 * u);
                *(float4*)(fb + 4 * u) = *(const float4*)(Wp + kc + 4 * u);
            }
            __nv_bfloat162 ha[8], la[8], hb[8], lb[8];
#pragma unroll
            for (int e = 0; e < 8; e++) {
                float a0 = fa[2 * e], a1 = fa[2 * e + 1];
                ha[e] = __floats2bfloat162_rn(a0, a1);
                la[e] = __floats2bfloat162_rn(a0 - __low2float(ha[e]),
                                              a1 - __high2float(ha[e]));
                float b0 = fb[2 * e], b1 = fb[2 * e + 1];
                hb[e] = __floats2bfloat162_rn(b0, b1);
                lb[e] = __floats2bfloat162_rn(b0 - __low2float(hb[e]),
                                              b1 - __high2float(hb[e]));
            }
            *(uint4*)(AhS)     = ((uint4*)ha)[0];
            *(uint4*)(AhS + 8) = ((uint4*)ha)[1];
            *(uint4*)(AlS)     = ((uint4*)la)[0];
            *(uint4*)(AlS + 8) = ((uint4*)la)[1];
            *(uint4*)(BhS)     = ((uint4*)hb)[0];
            *(uint4*)(BhS + 8) = ((uint4*)hb)[1];
            *(uint4*)(BlS)     = ((uint4*)lb)[0];
            *(uint4*)(BlS + 8) = ((uint4*)lb)[1];
        }
        __syncthreads();

        // ---- compute: 2 k16 steps ----
#pragma unroll
        for (int ks = 0; ks < 2; ks++) {
            const uint32_t ko = (uint32_t)(ks * 32);  // 16 halves = 32 bytes
            uint32_t ah[4][4], al[4][4];
#pragma unroll
            for (int am = 0; am < 4; am++) {
                const uint32_t o = a_off + (uint32_t)(am * 16) * GROW + ko;
                ldmx4(ah[am], AhB + o);
                ldmx4(al[am], AlB + o);
            }
            uint32_t bh[4][2], bl[4][2];
#pragma unroll
            for (int an = 0; an < 4; an++) {
                const uint32_t o = b_off + (uint32_t)(an * 8) * GROW + ko;
                ldmx2(bh[an], BhB + o);
                ldmx2(bl[an], BlB + o);
            }
#pragma unroll
            for (int am = 0; am < 4; am++)
#pragma unroll
                for (int an = 0; an < 4; an++) {
                    mma_bf16(acc[am][an], ah[am], bh[an]);
                    mma_bf16(acc[am][an], ah[am], bl[an]);
                    mma_bf16(acc[am][an], al[am], bh[an]);
                }
        }
        __syncthreads();
    }

    // ---- epilogue: bias add + store ----
    const int gr = lane >> 2;          // 0..7
    const int gc = (lane & 3) * 2;     // 0,2,4,6
#pragma unroll
    for (int am = 0; am < 4; am++) {
#pragma unroll
        for (int an = 0; an < 4; an++) {
            const int row = bm + warp_m * 64 + am * 16 + gr;
            const int col = bn + warp_n * 32 + an * 8 + gc;
            const float b0 = __ldg(&bias[col]);
            const float b1 = __ldg(&bias[col + 1]);
            float2 o0 = make_float2(acc[am][an][0] + b0, acc[am][an][1] + b1);
            float2 o1 = make_float2(acc[am][an][2] + b0, acc[am][an][3] + b1);
            *(float2*)&Y[(size_t)row * D_MODEL + col]       = o0;
            *(float2*)&Y[(size_t)(row + 8) * D_MODEL + col] = o1;
        }
    }
}

// ---------------------------------------------------------------------------
// Flash attention, fp32 SIMT (unchanged from round 1 — next round's target)
// ---------------------------------------------------------------------------
#define BQ   64
#define BKV  64
#define PSTR 68
#define ATTN_SMEM_FLOATS (HEAD_DIM*BQ + HEAD_DIM*BKV + BKV*HEAD_DIM + BKV*PSTR + 2*BQ)
#define ATTN_SMEM_BYTES  (ATTN_SMEM_FLOATS * 4)

__global__ __launch_bounds__(256) void flash_attn_kernel(
    const float* __restrict__ Qg, const float* __restrict__ Kg,
    const float* __restrict__ Vg, const int* __restrict__ mask,
    float* __restrict__ Og)
{
    extern __shared__ float smf[];
    float* Qs  = smf;
    float* Ks  = Qs + HEAD_DIM * BQ;
    float* Vs  = Ks + HEAD_DIM * BKV;
    float* Ps  = Vs + BKV * HEAD_DIM;
    float* m_s = Ps + BKV * PSTR;
    float* l_s = m_s + BQ;

    const int tid = threadIdx.x;
    const int ty  = tid >> 4;
    const int tx  = tid & 15;
    const int i0  = ty * 4;
    const int c0  = tx * 4;

    const int qt = blockIdx.x;
    const int h  = blockIdx.y;
    const int b  = blockIdx.z;
    const int qbase = qt * BQ;
    const float scale = 0.125f;

    {
        const int r   = tid >> 2;
        const int seg = (tid & 3) * 16;
        const float* src = Qg + ((size_t)(b * SEQ + qbase + r)) * D_MODEL + h * HEAD_DIM + seg;
#pragma unroll
        for (int u = 0; u < 4; u++) {
            float4 v = *(const float4*)(src + 4 * u);
            const int d = seg + 4 * u;
            Qs[(d + 0) * BQ + r] = v.x;
            Qs[(d + 1) * BQ + r] = v.y;
            Qs[(d + 2) * BQ + r] = v.z;
            Qs[(d + 3) * BQ + r] = v.w;
        }
    }
    if (tid < BQ) { m_s[tid] = -CUDART_INF_F; l_s[tid] = 0.f; }

    float acc[4][4];
#pragma unroll
    for (int i = 0; i < 4; i++)
#pragma unroll
        for (int j = 0; j < 4; j++) acc[i][j] = 0.f;

    for (int kt = 0; kt < SEQ; kt += BKV) {
        __syncthreads();
        {
            const int r   = tid >> 2;
            const int seg = (tid & 3) * 16;
            const float* ksrc = Kg + ((size_t)(b * SEQ + kt + r)) * D_MODEL + h * HEAD_DIM + seg;
            const float* vsrc = Vg + ((size_t)(b * SEQ + kt + r)) * D_MODEL + h * HEAD_DIM + seg;
#pragma unroll
            for (int u = 0; u < 4; u++) {
                const int d = seg + 4 * u;
                float4 v = *(const float4*)(ksrc + 4 * u);
                Ks[(d + 0) * BKV + r] = v.x;
                Ks[(d + 1) * BKV + r] = v.y;
                Ks[(d + 2) * BKV + r] = v.z;
                Ks[(d + 3) * BKV + r] = v.w;
                float4 w = *(const float4*)(vsrc + 4 * u);
                *(float4*)&Vs[r * HEAD_DIM + d] = w;
            }
        }
        __syncthreads();

        float s[4][4];
#pragma unroll
        for (int i = 0; i < 4; i++)
#pragma unroll
            for (int j = 0; j < 4; j++) s[i][j] = 0.f;

#pragma unroll 8
        for (int d = 0; d < HEAD_DIM; d++) {
            float4 ra = *(const float4*)&Qs[d * BQ + i0];
            float4 rb = *(const float4*)&Ks[d * BKV + c0];
            float aa[4] = {ra.x, ra.y, ra.z, ra.w};
            float bb[4] = {rb.x, rb.y, rb.z, rb.w};
#pragma unroll
            for (int i = 0; i < 4; i++)
#pragma unroll
                for (int j = 0; j < 4; j++)
                    s[i][j] = fmaf(aa[i], bb[j], s[i][j]);
        }

#pragma unroll
        for (int ii = 0; ii < 4; ii++) {
            const int q = qbase + i0 + ii;
            const int4 mm = *(const int4*)(mask + ((size_t)(b * SEQ + q)) * SEQ + kt + c0);
            s[ii][0] = mm.x ? s[ii][0] * scale : -1e30f;
            s[ii][1] = mm.y ? s[ii][1] * scale : -1e30f;
            s[ii][2] = mm.z ? s[ii][2] * scale : -1e30f;
            s[ii][3] = mm.w ? s[ii][3] * scale : -1e30f;
        }

#pragma unroll
        for (int ii = 0; ii < 4; ii++) {
            float rmax = fmaxf(fmaxf(s[ii][0], s[ii][1]), fmaxf(s[ii][2], s[ii][3]));
            rmax = fmaxf(rmax, __shfl_xor_sync(0xffffffffu, rmax, 1));
            rmax = fmaxf(rmax, __shfl_xor_sync(0xffffffffu, rmax, 2));
            rmax = fmaxf(rmax, __shfl_xor_sync(0xffffffffu, rmax, 4));
            rmax = fmaxf(rmax, __shfl_xor_sync(0xffffffffu, rmax, 8));

            const float m_old = m_s[i0 + ii];
            const float m_new = fmaxf(m_old, rmax);

            float p0 = __expf(s[ii][0] - m_new);
            float p1 = __expf(s[ii][1] - m_new);
            float p2 = __expf(s[ii][2] - m_new);
            float p3 = __expf(s[ii][3] - m_new);
            float rsum = p0 + p1 + p2 + p3;
            rsum += __shfl_xor_sync(0xffffffffu, rsum, 1);
            rsum += __shfl_xor_sync(0xffffffffu, rsum, 2);
            rsum += __shfl_xor_sync(0xffffffffu, rsum, 4);
            rsum += __shfl_xor_sync(0xffffffffu, rsum, 8);

            const float alpha = __expf(m_old - m_new);
            acc[ii][0] *= alpha; acc[ii][1] *= alpha;
            acc[ii][2] *= alpha; acc[ii][3] *= alpha;

            __syncwarp();
            if (tx == 0) {
                m_s[i0 + ii] = m_new;
                l_s[i0 + ii] = l_s[i0 + ii] * alpha + rsum;
            }

            Ps[(c0 + 0) * PSTR + i0 + ii] = p0;
            Ps[(c0 + 1) * PSTR + i0 + ii] = p1;
            Ps[(c0 + 2) * PSTR + i0 + ii] = p2;
            Ps[(c0 + 3) * PSTR + i0 + ii] = p3;
        }
        __syncthreads();

#pragma unroll 8
        for (int j = 0; j < BKV; j++) {
            float4 ra = *(const float4*)&Ps[j * PSTR + i0];
            float4 rb = *(const float4*)&Vs[j * HEAD_DIM + c0];
            float aa[4] = {ra.x, ra.y, ra.z, ra.w};
            float bb[4] = {rb.x, rb.y, rb.z, rb.w};
#pragma unroll
            for (int i = 0; i < 4; i++)
#pragma unroll
                for (int jj = 0; jj < 4; jj++)
                    acc[i][jj] = fmaf(aa[i], bb[jj], acc[i][jj]);
        }
    }

#pragma unroll
    for (int ii = 0; ii < 4; ii++) {
        const float inv = 1.0f / l_s[i0 + ii];
        float4 o = make_float4(acc[ii][0] * inv, acc[ii][1] * inv,
                               acc[ii][2] * inv, acc[ii][3] * inv);
        *(float4*)(Og + ((size_t)(b * SEQ + qbase + i0 + ii)) * D_MODEL + h * HEAD_DIM + c0) = o;
    }
}

// ---------------------------------------------------------------------------
// Launcher — inputs: query key value mask wq bq wk bk wv bv wo bo
// ---------------------------------------------------------------------------
extern "C" void kernel_launch(void* const* d_in, const int* in_sizes, int n_in,
                              void* d_out, int out_size)
{
    const float* query = (const float*)d_in[0];
    const float* key   = (const float*)d_in[1];
    const float* value = (const float*)d_in[2];
    const int*   mask  = (const int*)  d_in[3];
    const float* wq    = (const float*)d_in[4];
    const float* bq    = (const float*)d_in[5];
    const float* wk    = (const float*)d_in[6];
    const float* bk    = (const float*)d_in[7];
    const float* wv    = (const float*)d_in[8];
    const float* bv    = (const float*)d_in[9];
    const float* wo    = (const float*)d_in[10];
    const float* bo    = (const float*)d_in[11];
    float* out = (float*)d_out;

    float *Qb, *Kb, *Vb, *Ab;
    cudaGetSymbolAddress((void**)&Qb, g_Q);
    cudaGetSymbolAddress((void**)&Kb, g_K);
    cudaGetSymbolAddress((void**)&Vb, g_V);
    cudaGetSymbolAddress((void**)&Ab, g_att);

    cudaFuncSetAttribute(flash_attn_kernel,
                         cudaFuncAttributeMaxDynamicSharedMemorySize, ATTN_SMEM_BYTES);

    dim3 gg(D_MODEL / 128, M_TOT / 128);   // (8, 32)
    gemm_mma_kernel<<<gg, 256>>>(query, wq, bq, Qb);
    gemm_mma_kernel<<<gg, 256>>>(key,   wk, bk, Kb);
    gemm_mma_kernel<<<gg, 256>>>(value, wv, bv, Vb);

    dim3 ga(SEQ / BQ, N_HEADS, BATCH);     // (32, 16, 2)
    flash_attn_kernel<<<ga, 256, ATTN_SMEM_BYTES>>>(Qb, Kb, Vb, mask, Ab);

    gemm_mma_kernel<<<gg, 256>>>(Ab, wo, bo, out);
}

// round 4
// speedup vs baseline: 1.9540x; 1.4871x over previous
#include <cuda_runtime.h>
#include <cuda_bf16.h>
#include <math_constants.h>
#include <cstdint>

#define D_MODEL   1024
#define N_HEADS   16
#define HEAD_DIM  64
#define BATCH     2
#define SEQ       2048
#define M_TOT     (BATCH * SEQ)   // 4096
#define GK        1024

// ---------------------------------------------------------------------------
// Scratch (no cudaMalloc allowed)
// ---------------------------------------------------------------------------
__device__ float g_Q[M_TOT * D_MODEL];
__device__ float g_K[M_TOT * D_MODEL];
__device__ float g_V[M_TOT * D_MODEL];
__device__ float g_att[M_TOT * D_MODEL];

// ---------------------------------------------------------------------------
// Warp-MMA helpers (target-portable: ldmatrix sm_75+, bf16 mma sm_80+)
// ---------------------------------------------------------------------------
__device__ __forceinline__ uint32_t smem_to_u32(const void* smem_ptr) {
    uint32_t addr;
    asm("{ .reg .u64 tmp; cvta.to.shared.u64 tmp, %1; cvt.u32.u64 %0, tmp; }"
        : "=r"(addr) : "l"(smem_ptr));
    return addr;
}

__device__ __forceinline__ void ldmx4(uint32_t* r, uint32_t addr) {
    asm volatile("ldmatrix.sync.aligned.m8n8.x4.shared.b16 {%0,%1,%2,%3}, [%4];"
        : "=r"(r[0]), "=r"(r[1]), "=r"(r[2]), "=r"(r[3]) : "r"(addr));
}
__device__ __forceinline__ void ldmx4t(uint32_t* r, uint32_t addr) {
    asm volatile("ldmatrix.sync.aligned.m8n8.x4.trans.shared.b16 {%0,%1,%2,%3}, [%4];"
        : "=r"(r[0]), "=r"(r[1]), "=r"(r[2]), "=r"(r[3]) : "r"(addr));
}
__device__ __forceinline__ void ldmx2(uint32_t* r, uint32_t addr) {
    asm volatile("ldmatrix.sync.aligned.m8n8.x2.shared.b16 {%0,%1}, [%2];"
        : "=r"(r[0]), "=r"(r[1]) : "r"(addr));
}

__device__ __forceinline__ void mma_bf16(float* d, const uint32_t* a, const uint32_t* b) {
    asm volatile(
        "mma.sync.aligned.m16n8k16.row.col.f32.bf16.bf16.f32 "
        "{%0,%1,%2,%3}, {%4,%5,%6,%7}, {%8,%9}, {%0,%1,%2,%3};"
        : "+f"(d[0]), "+f"(d[1]), "+f"(d[2]), "+f"(d[3])
        : "r"(a[0]), "r"(a[1]), "r"(a[2]), "r"(a[3]), "r"(b[0]), "r"(b[1]));
}

// split fp32 pair -> hi/lo bf16x2 packed registers
__device__ __forceinline__ void split_pack(float x, float y, uint32_t& hi, uint32_t& lo) {
    __nv_bfloat162 h = __floats2bfloat162_rn(x, y);
    __nv_bfloat162 l = __floats2bfloat162_rn(x - __low2float(h), y - __high2float(h));
    hi = *reinterpret_cast<uint32_t*>(&h);
    lo = *reinterpret_cast<uint32_t*>(&l);
}

// ---------------------------------------------------------------------------
// Split-bf16 HMMA GEMM (unchanged from round 3 — passing)
// ---------------------------------------------------------------------------
#define GSTR 40
#define GROW (GSTR * 2)

__global__ __launch_bounds__(256) void gemm_mma_kernel(
    const float* __restrict__ X, const float* __restrict__ W,
    const float* __restrict__ bias, float* __restrict__ Y)
{
    __shared__ __align__(16) __nv_bfloat16 Ah[128 * GSTR], Al[128 * GSTR];
    __shared__ __align__(16) __nv_bfloat16 Bh[128 * GSTR], Bl[128 * GSTR];

    const int tid    = threadIdx.x;
    const int wid    = tid >> 5;
    const int lane   = tid & 31;
    const int warp_m = wid & 1;
    const int warp_n = wid >> 1;
    const int bm = blockIdx.y * 128;
    const int bn = blockIdx.x * 128;

    float acc[4][4][4];
#pragma unroll
    for (int i = 0; i < 4; i++)
#pragma unroll
        for (int j = 0; j < 4; j++)
#pragma unroll
            for (int k = 0; k < 4; k++) acc[i][j][k] = 0.f;

    const int lrow = tid >> 1;
    const int lseg = (tid & 1) * 16;
    const float* Xp = X + (size_t)(bm + lrow) * GK + lseg;
    const float* Wp = W + (size_t)(bn + lrow) * GK + lseg;

    const uint32_t AhB = smem_to_u32(Ah), AlB = smem_to_u32(Al);
    const uint32_t BhB = smem_to_u32(Bh), BlB = smem_to_u32(Bl);

    const uint32_t a_off = ((uint32_t)(lane & 15) * GSTR + (uint32_t)(lane >> 4) * 8) * 2
                         + (uint32_t)(warp_m * 64) * GROW;
    const uint32_t b_off = ((uint32_t)(lane & 7) * GSTR + (uint32_t)((lane >> 3) & 1) * 8) * 2
                         + (uint32_t)(warp_n * 32) * GROW;

    __nv_bfloat16* AhS = Ah + lrow * GSTR + lseg;
    __nv_bfloat16* AlS = Al + lrow * GSTR + lseg;
    __nv_bfloat16* BhS = Bh + lrow * GSTR + lseg;
    __nv_bfloat16* BlS = Bl + lrow * GSTR + lseg;

    for (int kc = 0; kc < GK; kc += 32) {
        {
            float fa[16], fb[16];
#pragma unroll
            for (int u = 0; u < 4; u++) {
                *(float4*)(fa + 4 * u) = *(const float4*)(Xp + kc + 4 * u);
                *(float4*)(fb + 4 * u) = *(const float4*)(Wp + kc + 4 * u);
            }
            __nv_bfloat162 ha[8], la[8], hb[8], lb[8];
#pragma unroll
            for (int e = 0; e < 8; e++) {
                float a0 = fa[2 * e], a1 = fa[2 * e + 1];
                ha[e] = __floats2bfloat162_rn(a0, a1);
                la[e] = __floats2bfloat162_rn(a0 - __low2float(ha[e]),
                                              a1 - __high2float(ha[e]));
                float b0 = fb[2 * e], b1 = fb[2 * e + 1];
                hb[e] = __floats2bfloat162_rn(b0, b1);
                lb[e] = __floats2bfloat162_rn(b0 - __low2float(hb[e]),
                                              b1 - __high2float(hb[e]));
            }
            *(uint4*)(AhS)     = ((uint4*)ha)[0];
            *(uint4*)(AhS + 8) = ((uint4*)ha)[1];
            *(uint4*)(AlS)     = ((uint4*)la)[0];
            *(uint4*)(AlS + 8) = ((uint4*)la)[1];
            *(uint4*)(BhS)     = ((uint4*)hb)[0];
            *(uint4*)(BhS + 8) = ((uint4*)hb)[1];
            *(uint4*)(BlS)     = ((uint4*)lb)[0];
            *(uint4*)(BlS + 8) = ((uint4*)lb)[1];
        }
        __syncthreads();

#pragma unroll
        for (int ks = 0; ks < 2; ks++) {
            const uint32_t ko = (uint32_t)(ks * 32);
            uint32_t ah[4][4], al[4][4];
#pragma unroll
            for (int am = 0; am < 4; am++) {
                const uint32_t o = a_off + (uint32_t)(am * 16) * GROW + ko;
                ldmx4(ah[am], AhB + o);
                ldmx4(al[am], AlB + o);
            }
            uint32_t bh[4][2], bl[4][2];
#pragma unroll
            for (int an = 0; an < 4; an++) {
                const uint32_t o = b_off + (uint32_t)(an * 8) * GROW + ko;
                ldmx2(bh[an], BhB + o);
                ldmx2(bl[an], BlB + o);
            }
#pragma unroll
            for (int am = 0; am < 4; am++)
#pragma unroll
                for (int an = 0; an < 4; an++) {
                    mma_bf16(acc[am][an], ah[am], bh[an]);
                    mma_bf16(acc[am][an], ah[am], bl[an]);
                    mma_bf16(acc[am][an], al[am], bh[an]);
                }
        }
        __syncthreads();
    }

    const int gr = lane >> 2;
    const int gc = (lane & 3) * 2;
#pragma unroll
    for (int am = 0; am < 4; am++) {
#pragma unroll
        for (int an = 0; an < 4; an++) {
            const int row = bm + warp_m * 64 + am * 16 + gr;
            const int col = bn + warp_n * 32 + an * 8 + gc;
            const float b0 = __ldg(&bias[col]);
            const float b1 = __ldg(&bias[col + 1]);
            float2 o0 = make_float2(acc[am][an][0] + b0, acc[am][an][1] + b1);
            float2 o1 = make_float2(acc[am][an][2] + b0, acc[am][an][3] + b1);
            *(float2*)&Y[(size_t)row * D_MODEL + col]       = o0;
            *(float2*)&Y[(size_t)(row + 8) * D_MODEL + col] = o1;
        }
    }
}

// ---------------------------------------------------------------------------
// HMMA flash attention, split-bf16 for both S=QK^T and O=PV.
// CTA = 64 queries of one (b,h); 4 warps x 16 q-rows; softmax in registers.
// smem: Qh/Ql, Kh/Kl, Vh/Vl (64x64 halves, stride 72), mask (64x64 int, stride 68)
// ---------------------------------------------------------------------------
#define ASTR 72                     // halves per row
#define AROW (ASTR * 2)             // 144 bytes
#define OFF_QH 0
#define OFF_QL (OFF_QH + 64 * AROW)
#define OFF_KH (OFF_QL + 64 * AROW)
#define OFF_KL (OFF_KH + 64 * AROW)
#define OFF_VH (OFF_KL + 64 * AROW)
#define OFF_VL (OFF_VH + 64 * AROW)
#define OFF_MK (OFF_VL + 64 * AROW)
#define MSTR   68
#define ATTN_SMEM_BYTES (OFF_MK + 64 * MSTR * 4)   // 72704

// load 32 fp32 (one row-half) -> hi/lo bf16 smem
__device__ __forceinline__ void conv_row32(const float* __restrict__ src,
                                           char* dstH, char* dstL,
                                           int row, int seg)
{
    char* pH = dstH + (row * ASTR + seg) * 2;
    char* pL = dstL + (row * ASTR + seg) * 2;
#pragma unroll
    for (int u = 0; u < 4; u++) {
        float4 f0 = *(const float4*)(src + u * 8);
        float4 f1 = *(const float4*)(src + u * 8 + 4);
        float f[8] = {f0.x, f0.y, f0.z, f0.w, f1.x, f1.y, f1.z, f1.w};
        __nv_bfloat162 h[4], l[4];
#pragma unroll
        for (int e = 0; e < 4; e++) {
            h[e] = __floats2bfloat162_rn(f[2 * e], f[2 * e + 1]);
            l[e] = __floats2bfloat162_rn(f[2 * e]     - __low2float(h[e]),
                                         f[2 * e + 1] - __high2float(h[e]));
        }
        *(uint4*)(pH + u * 16) = *(uint4*)h;
        *(uint4*)(pL + u * 16) = *(uint4*)l;
    }
}

__global__ __launch_bounds__(128) void flash_attn_mma_kernel(
    const float* __restrict__ Qg, const float* __restrict__ Kg,
    const float* __restrict__ Vg, const int* __restrict__ mask,
    float* __restrict__ Og)
{
    extern __shared__ char sm[];
    const uint32_t smb = smem_to_u32(sm);
    int* mk = (int*)(sm + OFF_MK);

    const int tid  = threadIdx.x;
    const int w    = tid >> 5;
    const int lane = tid & 31;
    const int qt = blockIdx.x, h = blockIdx.y, b = blockIdx.z;
    const int qbase = qt * 64;
    const float scale = 0.125f;

    // loader mapping: thread t handles row t>>1, 32-col half (t&1)*32
    const int lrow = tid >> 1;
    const int lseg = (tid & 1) * 32;

    // ---- Q tile load+convert (once) ----
    {
        const float* src = Qg + (size_t)(b * SEQ + qbase + lrow) * D_MODEL + h * HEAD_DIM + lseg;
        float buf[32];
#pragma unroll
        for (int u = 0; u < 8; u++) *(float4*)(buf + 4 * u) = *(const float4*)(src + 4 * u);
        conv_row32(buf, sm + OFF_QH, sm + OFF_QL, lrow, lseg);
    }
    __syncthreads();

    // ---- Q A-frags in registers (4 k-steps) ----
    uint32_t qh[4][4], ql[4][4];
    {
        const uint32_t ao = (uint32_t)((w * 16 + (lane & 15)) * AROW + (lane >> 4) * 16);
#pragma unroll
        for (int kk = 0; kk < 4; kk++) {
            ldmx4(qh[kk], smb + OFF_QH + ao + kk * 32);
            ldmx4(ql[kk], smb + OFF_QL + ao + kk * 32);
        }
    }

    float accO[8][4];
#pragma unroll
    for (int t = 0; t < 8; t++)
#pragma unroll
        for (int i = 0; i < 4; i++) accO[t][i] = 0.f;
    float mrow0 = -1e30f, mrow1 = -1e30f, lrow0 = 0.f, lrow1 = 0.f;

    // per-lane ldmatrix offsets
    const uint32_t k_off = (uint32_t)((((lane >> 4) << 3) + (lane & 7)) * AROW
                                      + ((lane >> 3) & 1) * 16);
    const uint32_t v_off = (uint32_t)(((((lane >> 3) & 1) * 8 + (lane & 7)) * AROW)
                                      + ((lane >> 4) << 4));
    const int mrow = w * 16 + (lane >> 2);
    const int mcol = 2 * (lane & 3);

    for (int kt = 0; kt < SEQ; kt += 64) {
        __syncthreads();
        // ---- K,V,mask tile load ----
        {
            const size_t gro = (size_t)(b * SEQ + kt + lrow) * D_MODEL + h * HEAD_DIM + lseg;
            float buf[32];
#pragma unroll
            for (int u = 0; u < 8; u++) *(float4*)(buf + 4 * u) = *(const float4*)(Kg + gro + 4 * u);
            conv_row32(buf, sm + OFF_KH, sm + OFF_KL, lrow, lseg);
#pragma unroll
            for (int u = 0; u < 8; u++) *(float4*)(buf + 4 * u) = *(const float4*)(Vg + gro + 4 * u);
            conv_row32(buf, sm + OFF_VH, sm + OFF_VL, lrow, lseg);

            const int* msrc = mask + (size_t)(b * SEQ + qbase + lrow) * SEQ + kt + lseg;
            int* mdst = mk + lrow * MSTR + lseg;
#pragma unroll
            for (int u = 0; u < 8; u++) *(int4*)(mdst + 4 * u) = *(const int4*)(msrc + 4 * u);
        }
        __syncthreads();

        // ---- S = Q K^T ----
        float s[8][4];
#pragma unroll
        for (int t = 0; t < 8; t++)
#pragma unroll
            for (int i = 0; i < 4; i++) s[t][i] = 0.f;

#pragma unroll
        for (int kk = 0; kk < 4; kk++) {
#pragma unroll
            for (int p = 0; p < 4; p++) {
                uint32_t bh[4], bl[4];
                const uint32_t o = k_off + (uint32_t)(p * 16) * AROW + kk * 32;
                ldmx4(bh, smb + OFF_KH + o);
                ldmx4(bl, smb + OFF_KL + o);
                mma_bf16(s[2 * p],     qh[kk], bh);
                mma_bf16(s[2 * p],     qh[kk], bl);
                mma_bf16(s[2 * p],     ql[kk], bh);
                mma_bf16(s[2 * p + 1], qh[kk], bh + 2);
                mma_bf16(s[2 * p + 1], qh[kk], bl + 2);
                mma_bf16(s[2 * p + 1], ql[kk], bh + 2);
            }
        }

        // ---- mask + scale ----
        const int* mb0 = mk + mrow * MSTR + mcol;
        const int* mb1 = mb0 + 8 * MSTR;
#pragma unroll
        for (int t = 0; t < 8; t++) {
            int2 m0 = *(const int2*)(mb0 + 8 * t);
            int2 m1 = *(const int2*)(mb1 + 8 * t);
            s[t][0] = m0.x ? s[t][0] * scale : -1e30f;
            s[t][1] = m0.y ? s[t][1] * scale : -1e30f;
            s[t][2] = m1.x ? s[t][2] * scale : -1e30f;
            s[t][3] = m1.y ? s[t][3] * scale : -1e30f;
        }

        // ---- online softmax (registers + 2 shfls) ----
        float mx0 = -1e30f, mx1 = -1e30f;
#pragma unroll
        for (int t = 0; t < 8; t++) {
            mx0 = fmaxf(mx0, fmaxf(s[t][0], s[t][1]));
            mx1 = fmaxf(mx1, fmaxf(s[t][2], s[t][3]));
        }
        mx0 = fmaxf(mx0, __shfl_xor_sync(0xffffffffu, mx0, 1));
        mx0 = fmaxf(mx0, __shfl_xor_sync(0xffffffffu, mx0, 2));
        mx1 = fmaxf(mx1, __shfl_xor_sync(0xffffffffu, mx1, 1));
        mx1 = fmaxf(mx1, __shfl_xor_sync(0xffffffffu, mx1, 2));

        const float mn0 = fmaxf(mrow0, mx0);
        const float mn1 = fmaxf(mrow1, mx1);
        const float a0 = __expf(mrow0 - mn0);
        const float a1 = __expf(mrow1 - mn1);
        mrow0 = mn0; mrow1 = mn1;

        float sum0 = 0.f, sum1 = 0.f;
#pragma unroll
        for (int t = 0; t < 8; t++) {
            s[t][0] = __expf(s[t][0] - mn0);
            s[t][1] = __expf(s[t][1] - mn0);
            s[t][2] = __expf(s[t][2] - mn1);
            s[t][3] = __expf(s[t][3] - mn1);
            sum0 += s[t][0] + s[t][1];
            sum1 += s[t][2] + s[t][3];
        }
        sum0 += __shfl_xor_sync(0xffffffffu, sum0, 1);
        sum0 += __shfl_xor_sync(0xffffffffu, sum0, 2);
        sum1 += __shfl_xor_sync(0xffffffffu, sum1, 1);
        sum1 += __shfl_xor_sync(0xffffffffu, sum1, 2);
        lrow0 = lrow0 * a0 + sum0;
        lrow1 = lrow1 * a1 + sum1;

#pragma unroll
        for (int t = 0; t < 8; t++) {
            accO[t][0] *= a0; accO[t][1] *= a0;
            accO[t][2] *= a1; accO[t][3] *= a1;
        }

        // ---- O += P V ----
#pragma unroll
        for (int kk = 0; kk < 4; kk++) {
            uint32_t pah[4], pal[4];
            split_pack(s[2 * kk][0],     s[2 * kk][1],     pah[0], pal[0]);
            split_pack(s[2 * kk][2],     s[2 * kk][3],     pah[1], pal[1]);
            split_pack(s[2 * kk + 1][0], s[2 * kk + 1][1], pah[2], pal[2]);
            split_pack(s[2 * kk + 1][2], s[2 * kk + 1][3], pah[3], pal[3]);
#pragma unroll
            for (int jp = 0; jp < 4; jp++) {
                uint32_t vh[4], vl[4];
                const uint32_t o = v_off + (uint32_t)(kk * 16) * AROW + jp * 32;
                ldmx4t(vh, smb + OFF_VH + o);
                ldmx4t(vl, smb + OFF_VL + o);
                mma_bf16(accO[2 * jp],     pah, vh);
                mma_bf16(accO[2 * jp],     pah, vl);
                mma_bf16(accO[2 * jp],     pal, vh);
                mma_bf16(accO[2 * jp + 1], pah, vh + 2);
                mma_bf16(accO[2 * jp + 1], pah, vl + 2);
                mma_bf16(accO[2 * jp + 1], pal, vh + 2);
            }
        }
    }

    // ---- epilogue ----
    const float inv0 = 1.0f / lrow0;
    const float inv1 = 1.0f / lrow1;
    const int q0 = qbase + w * 16 + (lane >> 2);
    float* o0 = Og + (size_t)(b * SEQ + q0) * D_MODEL + h * HEAD_DIM + 2 * (lane & 3);
    float* o1 = o0 + 8 * D_MODEL;
#pragma unroll
    for (int t = 0; t < 8; t++) {
        *(float2*)(o0 + 8 * t) = make_float2(accO[t][0] * inv0, accO[t][1] * inv0);
        *(float2*)(o1 + 8 * t) = make_float2(accO[t][2] * inv1, accO[t][3] * inv1);
    }
}

// ---------------------------------------------------------------------------
// Launcher — inputs: query key value mask wq bq wk bk wv bv wo bo
// ---------------------------------------------------------------------------
extern "C" void kernel_launch(void* const* d_in, const int* in_sizes, int n_in,
                              void* d_out, int out_size)
{
    const float* query = (const float*)d_in[0];
    const float* key   = (const float*)d_in[1];
    const float* value = (const float*)d_in[2];
    const int*   mask  = (const int*)  d_in[3];
    const float* wq    = (const float*)d_in[4];
    const float* bq    = (const float*)d_in[5];
    const float* wk    = (const float*)d_in[6];
    const float* bk    = (const float*)d_in[7];
    const float* wv    = (const float*)d_in[8];
    const float* bv    = (const float*)d_in[9];
    const float* wo    = (const float*)d_in[10];
    const float* bo    = (const float*)d_in[11];
    float* out = (float*)d_out;

    float *Qb, *Kb, *Vb, *Ab;
    cudaGetSymbolAddress((void**)&Qb, g_Q);
    cudaGetSymbolAddress((void**)&Kb, g_K);
    cudaGetSymbolAddress((void**)&Vb, g_V);
    cudaGetSymbolAddress((void**)&Ab, g_att);

    cudaFuncSetAttribute(flash_attn_mma_kernel,
                         cudaFuncAttributeMaxDynamicSharedMemorySize, ATTN_SMEM_BYTES);

    dim3 gg(D_MODEL / 128, M_TOT / 128);   // (8, 32)
    gemm_mma_kernel<<<gg, 256>>>(query, wq, bq, Qb);
    gemm_mma_kernel<<<gg, 256>>>(key,   wk, bk, Kb);
    gemm_mma_kernel<<<gg, 256>>>(value, wv, bv, Vb);

    dim3 ga(SEQ / 64, N_HEADS, BATCH);     // (32, 16, 2)
    flash_attn_mma_kernel<<<ga, 128, ATTN_SMEM_BYTES>>>(Qb, Kb, Vb, mask, Ab);

    gemm_mma_kernel<<<gg, 256>>>(Ab, wo, bo, out);
}

// round 5
// speedup vs baseline: 2.4304x; 1.2438x over previous
#include <cuda_runtime.h>
#include <cuda_bf16.h>
#include <math_constants.h>
#include <cstdint>

#define D_MODEL   1024
#define N_HEADS   16
#define HEAD_DIM  64
#define BATCH     2
#define SEQ       2048
#define M_TOT     (BATCH * SEQ)   // 4096
#define GK        1024

// ---------------------------------------------------------------------------
// Scratch (no cudaMalloc allowed)
// ---------------------------------------------------------------------------
__device__ __nv_bfloat16 g_Qh[M_TOT * D_MODEL];
__device__ __nv_bfloat16 g_Ql[M_TOT * D_MODEL];
__device__ __nv_bfloat16 g_Kh[M_TOT * D_MODEL];
__device__ __nv_bfloat16 g_Kl[M_TOT * D_MODEL];
__device__ __nv_bfloat16 g_Vh[M_TOT * D_MODEL];
__device__ __nv_bfloat16 g_Vl[M_TOT * D_MODEL];
__device__ float         g_att[M_TOT * D_MODEL];
__device__ unsigned char g_mflag[BATCH * 32 * 32];   // per 64x64 mask tile

// ---------------------------------------------------------------------------
// Warp-MMA helpers (target-portable: ldmatrix sm_75+, bf16 mma sm_80+)
// ---------------------------------------------------------------------------
__device__ __forceinline__ uint32_t smem_to_u32(const void* smem_ptr) {
    uint32_t addr;
    asm("{ .reg .u64 tmp; cvta.to.shared.u64 tmp, %1; cvt.u32.u64 %0, tmp; }"
        : "=r"(addr) : "l"(smem_ptr));
    return addr;
}
__device__ __forceinline__ void ldmx4(uint32_t* r, uint32_t addr) {
    asm volatile("ldmatrix.sync.aligned.m8n8.x4.shared.b16 {%0,%1,%2,%3}, [%4];"
        : "=r"(r[0]), "=r"(r[1]), "=r"(r[2]), "=r"(r[3]) : "r"(addr));
}
__device__ __forceinline__ void ldmx4t(uint32_t* r, uint32_t addr) {
    asm volatile("ldmatrix.sync.aligned.m8n8.x4.trans.shared.b16 {%0,%1,%2,%3}, [%4];"
        : "=r"(r[0]), "=r"(r[1]), "=r"(r[2]), "=r"(r[3]) : "r"(addr));
}
__device__ __forceinline__ void ldmx2(uint32_t* r, uint32_t addr) {
    asm volatile("ldmatrix.sync.aligned.m8n8.x2.shared.b16 {%0,%1}, [%2];"
        : "=r"(r[0]), "=r"(r[1]) : "r"(addr));
}
__device__ __forceinline__ void mma_bf16(float* d, const uint32_t* a, const uint32_t* b) {
    asm volatile(
        "mma.sync.aligned.m16n8k16.row.col.f32.bf16.bf16.f32 "
        "{%0,%1,%2,%3}, {%4,%5,%6,%7}, {%8,%9}, {%0,%1,%2,%3};"
        : "+f"(d[0]), "+f"(d[1]), "+f"(d[2]), "+f"(d[3])
        : "r"(a[0]), "r"(a[1]), "r"(a[2]), "r"(a[3]), "r"(b[0]), "r"(b[1]));
}
__device__ __forceinline__ void split_pack(float x, float y, uint32_t& hi, uint32_t& lo) {
    __nv_bfloat162 h = __floats2bfloat162_rn(x, y);
    __nv_bfloat162 l = __floats2bfloat162_rn(x - __low2float(h), y - __high2float(h));
    hi = *reinterpret_cast<uint32_t*>(&h);
    lo = *reinterpret_cast<uint32_t*>(&l);
}
__device__ __forceinline__ void cpa16(uint32_t s, const void* g) {
    asm volatile("cp.async.ca.shared.global [%0], [%1], 16;" :: "r"(s), "l"(g));
}
#define CP_COMMIT() asm volatile("cp.async.commit_group;" ::: "memory")
#define CP_WAIT0()  asm volatile("cp.async.wait_group 0;" ::: "memory")

// ---------------------------------------------------------------------------
// Split-bf16 HMMA GEMM. SPLIT_OUT: write bf16 hi/lo buffers (for Q/K/V);
// else write fp32 + nothing.
// ---------------------------------------------------------------------------
#define GSTR 40
#define GROW (GSTR * 2)

template<bool SPLIT_OUT>
__global__ __launch_bounds__(256) void gemm_mma_kernel(
    const float* __restrict__ X, const float* __restrict__ W,
    const float* __restrict__ bias, float* __restrict__ Yf,
    __nv_bfloat16* __restrict__ Yh, __nv_bfloat16* __restrict__ Yl)
{
    __shared__ __align__(16) __nv_bfloat16 Ah[128 * GSTR], Al[128 * GSTR];
    __shared__ __align__(16) __nv_bfloat16 Bh[128 * GSTR], Bl[128 * GSTR];

    const int tid    = threadIdx.x;
    const int wid    = tid >> 5;
    const int lane   = tid & 31;
    const int warp_m = wid & 1;
    const int warp_n = wid >> 1;
    const int bm = blockIdx.y * 128;
    const int bn = blockIdx.x * 128;

    float acc[4][4][4];
#pragma unroll
    for (int i = 0; i < 4; i++)
#pragma unroll
        for (int j = 0; j < 4; j++)
#pragma unroll
            for (int k = 0; k < 4; k++) acc[i][j][k] = 0.f;

    const int lrow = tid >> 1;
    const int lseg = (tid & 1) * 16;
    const float* Xp = X + (size_t)(bm + lrow) * GK + lseg;
    const float* Wp = W + (size_t)(bn + lrow) * GK + lseg;

    const uint32_t AhB = smem_to_u32(Ah), AlB = smem_to_u32(Al);
    const uint32_t BhB = smem_to_u32(Bh), BlB = smem_to_u32(Bl);

    const uint32_t a_off = ((uint32_t)(lane & 15) * GSTR + (uint32_t)(lane >> 4) * 8) * 2
                         + (uint32_t)(warp_m * 64) * GROW;
    const uint32_t b_off = ((uint32_t)(lane & 7) * GSTR + (uint32_t)((lane >> 3) & 1) * 8) * 2
                         + (uint32_t)(warp_n * 32) * GROW;

    __nv_bfloat16* AhS = Ah + lrow * GSTR + lseg;
    __nv_bfloat16* AlS = Al + lrow * GSTR + lseg;
    __nv_bfloat16* BhS = Bh + lrow * GSTR + lseg;
    __nv_bfloat16* BlS = Bl + lrow * GSTR + lseg;

    for (int kc = 0; kc < GK; kc += 32) {
        {
            float fa[16], fb[16];
#pragma unroll
            for (int u = 0; u < 4; u++) {
                *(float4*)(fa + 4 * u) = *(const float4*)(Xp + kc + 4 * u);
                *(float4*)(fb + 4 * u) = *(const float4*)(Wp + kc + 4 * u);
            }
            __nv_bfloat162 ha[8], la[8], hb[8], lb[8];
#pragma unroll
            for (int e = 0; e < 8; e++) {
                float a0 = fa[2 * e], a1 = fa[2 * e + 1];
                ha[e] = __floats2bfloat162_rn(a0, a1);
                la[e] = __floats2bfloat162_rn(a0 - __low2float(ha[e]),
                                              a1 - __high2float(ha[e]));
                float b0 = fb[2 * e], b1 = fb[2 * e + 1];
                hb[e] = __floats2bfloat162_rn(b0, b1);
                lb[e] = __floats2bfloat162_rn(b0 - __low2float(hb[e]),
                                              b1 - __high2float(hb[e]));
            }
            *(uint4*)(AhS)     = ((uint4*)ha)[0];
            *(uint4*)(AhS + 8) = ((uint4*)ha)[1];
            *(uint4*)(AlS)     = ((uint4*)la)[0];
            *(uint4*)(AlS + 8) = ((uint4*)la)[1];
            *(uint4*)(BhS)     = ((uint4*)hb)[0];
            *(uint4*)(BhS + 8) = ((uint4*)hb)[1];
            *(uint4*)(BlS)     = ((uint4*)lb)[0];
            *(uint4*)(BlS + 8) = ((uint4*)lb)[1];
        }
        __syncthreads();

#pragma unroll
        for (int ks = 0; ks < 2; ks++) {
            const uint32_t ko = (uint32_t)(ks * 32);
            uint32_t ah[4][4], al[4][4];
#pragma unroll
            for (int am = 0; am < 4; am++) {
                const uint32_t o = a_off + (uint32_t)(am * 16) * GROW + ko;
                ldmx4(ah[am], AhB + o);
                ldmx4(al[am], AlB + o);
            }
            uint32_t bh[4][2], bl[4][2];
#pragma unroll
            for (int an = 0; an < 4; an++) {
                const uint32_t o = b_off + (uint32_t)(an * 8) * GROW + ko;
                ldmx2(bh[an], BhB + o);
                ldmx2(bl[an], BlB + o);
            }
#pragma unroll
            for (int am = 0; am < 4; am++)
#pragma unroll
                for (int an = 0; an < 4; an++) {
                    mma_bf16(acc[am][an], ah[am], bh[an]);
                    mma_bf16(acc[am][an], ah[am], bl[an]);
                    mma_bf16(acc[am][an], al[am], bh[an]);
                }
        }
        __syncthreads();
    }

    const int gr = lane >> 2;
    const int gc = (lane & 3) * 2;
#pragma unroll
    for (int am = 0; am < 4; am++) {
#pragma unroll
        for (int an = 0; an < 4; an++) {
            const int row = bm + warp_m * 64 + am * 16 + gr;
            const int col = bn + warp_n * 32 + an * 8 + gc;
            const float b0 = __ldg(&bias[col]);
            const float b1 = __ldg(&bias[col + 1]);
            const float y00 = acc[am][an][0] + b0, y01 = acc[am][an][1] + b1;
            const float y10 = acc[am][an][2] + b0, y11 = acc[am][an][3] + b1;
            if (SPLIT_OUT) {
                uint32_t h0, l0, h1, l1;
                split_pack(y00, y01, h0, l0);
                split_pack(y10, y11, h1, l1);
                *(uint32_t*)&Yh[(size_t)row * D_MODEL + col]       = h0;
                *(uint32_t*)&Yl[(size_t)row * D_MODEL + col]       = l0;
                *(uint32_t*)&Yh[(size_t)(row + 8) * D_MODEL + col] = h1;
                *(uint32_t*)&Yl[(size_t)(row + 8) * D_MODEL + col] = l1;
            } else {
                *(float2*)&Yf[(size_t)row * D_MODEL + col]       = make_float2(y00, y01);
                *(float2*)&Yf[(size_t)(row + 8) * D_MODEL + col] = make_float2(y10, y11);
            }
        }
    }
}

// ---------------------------------------------------------------------------
// Mask tile flag pre-pass: flag[b][qt][kt] = 1 iff the 64x64 tile is all nonzero
// ---------------------------------------------------------------------------
__global__ __launch_bounds__(128) void mask_flags_kernel(
    const int* __restrict__ mask, unsigned char* __restrict__ flags)
{
    const int kt = blockIdx.x, qt = blockIdx.y, b = blockIdx.z;
    const int tid = threadIdx.x;
    const int row = tid >> 1;
    const int cs  = (tid & 1) * 32;
    const int* p = mask + (size_t)(b * SEQ + qt * 64 + row) * SEQ + kt * 64 + cs;
    int ok = 1;
#pragma unroll
    for (int u = 0; u < 8; u++) {
        int4 v = *(const int4*)(p + 4 * u);
        ok = ok && v.x && v.y && v.z && v.w;
    }
    __shared__ int s_all;
    if (tid == 0) s_all = 1;
    __syncthreads();
    if (!ok) atomicAnd(&s_all, 0);
    __syncthreads();
    if (tid == 0) flags[(b * 32 + qt) * 32 + kt] = (unsigned char)s_all;
}

// ---------------------------------------------------------------------------
// HMMA flash attention on precomputed bf16 hi/lo Q/K/V.
// CTA = 64 queries of one (b,h); 4 warps x 16 q-rows; softmax in registers.
// smem: Qh/Ql, Kh/Kl, Vh/Vl  (64 rows x 72-half stride)
// ---------------------------------------------------------------------------
#define ASTR 72
#define AROW (ASTR * 2)
#define OFF_QH 0
#define OFF_QL (OFF_QH + 64 * AROW)
#define OFF_KH (OFF_QL + 64 * AROW)
#define OFF_KL (OFF_KH + 64 * AROW)
#define OFF_VH (OFF_KL + 64 * AROW)
#define OFF_VL (OFF_VH + 64 * AROW)
#define ATTN_SMEM_BYTES (OFF_VL + 64 * AROW)   // 55296

__global__ __launch_bounds__(128, 4) void flash_attn_mma_kernel(
    const __nv_bfloat16* __restrict__ Qh_g, const __nv_bfloat16* __restrict__ Ql_g,
    const __nv_bfloat16* __restrict__ Kh_g, const __nv_bfloat16* __restrict__ Kl_g,
    const __nv_bfloat16* __restrict__ Vh_g, const __nv_bfloat16* __restrict__ Vl_g,
    const int* __restrict__ mask, const unsigned char* __restrict__ flags,
    float* __restrict__ Og)
{
    extern __shared__ char sm[];
    const uint32_t smb = smem_to_u32(sm);

    const int tid  = threadIdx.x;
    const int w    = tid >> 5;
    const int lane = tid & 31;
    const int qt = blockIdx.x, h = blockIdx.y, b = blockIdx.z;
    const int qbase = qt * 64;
    const float scale = 0.125f;

    // staging mapping: thread t -> row t>>1, 32-half segment (t&1)*32
    const int lrow = tid >> 1;
    const int lseg = (tid & 1) * 32;
    const uint32_t stg = (uint32_t)(lrow * AROW + lseg * 2);

    // ---- Q tile stage (once) ----
    {
        const size_t go = (size_t)(b * SEQ + qbase + lrow) * D_MODEL + h * HEAD_DIM + lseg;
#pragma unroll
        for (int u = 0; u < 4; u++) {
            cpa16(smb + OFF_QH + stg + 16 * u, Qh_g + go + 8 * u);
            cpa16(smb + OFF_QL + stg + 16 * u, Ql_g + go + 8 * u);
        }
        CP_COMMIT(); CP_WAIT0();
    }
    __syncthreads();

    float accO[8][4];
#pragma unroll
    for (int t = 0; t < 8; t++)
#pragma unroll
        for (int i = 0; i < 4; i++) accO[t][i] = 0.f;
    float mrw0 = -1e30f, mrw1 = -1e30f, lrw0 = 0.f, lrw1 = 0.f;

    const uint32_t q_off = (uint32_t)((w * 16 + (lane & 15)) * AROW + (lane >> 4) * 16);
    const uint32_t k_off = (uint32_t)((((lane >> 4) << 3) + (lane & 7)) * AROW
                                      + ((lane >> 3) & 1) * 16);
    const uint32_t v_off = (uint32_t)(((((lane >> 3) & 1) * 8 + (lane & 7)) * AROW)
                                      + ((lane >> 4) << 4));
    const int mrow = w * 16 + (lane >> 2);
    const int mcol = 2 * (lane & 3);
    const unsigned char* fp = flags + (b * 32 + qt) * 32;

    for (int kt = 0; kt < SEQ; kt += 64) {
        __syncthreads();   // previous tile's reads done
        {
            const size_t go = (size_t)(b * SEQ + kt + lrow) * D_MODEL + h * HEAD_DIM + lseg;
#pragma unroll
            for (int u = 0; u < 4; u++) {
                cpa16(smb + OFF_KH + stg + 16 * u, Kh_g + go + 8 * u);
                cpa16(smb + OFF_KL + stg + 16 * u, Kl_g + go + 8 * u);
                cpa16(smb + OFF_VH + stg + 16 * u, Vh_g + go + 8 * u);
                cpa16(smb + OFF_VL + stg + 16 * u, Vl_g + go + 8 * u);
            }
            CP_COMMIT(); CP_WAIT0();
        }
        __syncthreads();

        // ---- S = Q K^T ----
        float s[8][4];
#pragma unroll
        for (int t = 0; t < 8; t++)
#pragma unroll
            for (int i = 0; i < 4; i++) s[t][i] = 0.f;

#pragma unroll
        for (int kk = 0; kk < 4; kk++) {
            uint32_t qh[4], ql[4];
            ldmx4(qh, smb + OFF_QH + q_off + kk * 32);
            ldmx4(ql, smb + OFF_QL + q_off + kk * 32);
#pragma unroll
            for (int p = 0; p < 4; p++) {
                uint32_t bh[4], bl[4];
                const uint32_t o = k_off + (uint32_t)(p * 16) * AROW + kk * 32;
                ldmx4(bh, smb + OFF_KH + o);
                ldmx4(bl, smb + OFF_KL + o);
                mma_bf16(s[2 * p],     qh, bh);
                mma_bf16(s[2 * p],     qh, bl);
                mma_bf16(s[2 * p],     ql, bh);
                mma_bf16(s[2 * p + 1], qh, bh + 2);
                mma_bf16(s[2 * p + 1], qh, bl + 2);
                mma_bf16(s[2 * p + 1], ql, bh + 2);
            }
        }

        // ---- mask + scale (flag fast path; gmem fallback) ----
        if (__ldg(fp + (kt >> 6))) {
#pragma unroll
            for (int t = 0; t < 8; t++) {
                s[t][0] *= scale; s[t][1] *= scale;
                s[t][2] *= scale; s[t][3] *= scale;
            }
        } else {
            const int* mp0 = mask + (size_t)(b * SEQ + qbase + mrow) * SEQ + kt + mcol;
            const int* mp1 = mp0 + 8 * SEQ;
#pragma unroll
            for (int t = 0; t < 8; t++) {
                int2 m0 = *(const int2*)(mp0 + 8 * t);
                int2 m1 = *(const int2*)(mp1 + 8 * t);
                s[t][0] = m0.x ? s[t][0] * scale : -1e30f;
                s[t][1] = m0.y ? s[t][1] * scale : -1e30f;
                s[t][2] = m1.x ? s[t][2] * scale : -1e30f;
                s[t][3] = m1.y ? s[t][3] * scale : -1e30f;
            }
        }

        // ---- online softmax (registers + shfl) ----
        float mx0 = -1e30f, mx1 = -1e30f;
#pragma unroll
        for (int t = 0; t < 8; t++) {
            mx0 = fmaxf(mx0, fmaxf(s[t][0], s[t][1]));
            mx1 = fmaxf(mx1, fmaxf(s[t][2], s[t][3]));
        }
        mx0 = fmaxf(mx0, __shfl_xor_sync(0xffffffffu, mx0, 1));
        mx0 = fmaxf(mx0, __shfl_xor_sync(0xffffffffu, mx0, 2));
        mx1 = fmaxf(mx1, __shfl_xor_sync(0xffffffffu, mx1, 1));
        mx1 = fmaxf(mx1, __shfl_xor_sync(0xffffffffu, mx1, 2));

        const float mn0 = fmaxf(mrw0, mx0);
        const float mn1 = fmaxf(mrw1, mx1);
        const float a0 = __expf(mrw0 - mn0);
        const float a1 = __expf(mrw1 - mn1);
        mrw0 = mn0; mrw1 = mn1;

        float sum0 = 0.f, sum1 = 0.f;
#pragma unroll
        for (int t = 0; t < 8; t++) {
            s[t][0] = __expf(s[t][0] - mn0);
            s[t][1] = __expf(s[t][1] - mn0);
            s[t][2] = __expf(s[t][2] - mn1);
            s[t][3] = __expf(s[t][3] - mn1);
            sum0 += s[t][0] + s[t][1];
            sum1 += s[t][2] + s[t][3];
        }
        sum0 += __shfl_xor_sync(0xffffffffu, sum0, 1);
        sum0 += __shfl_xor_sync(0xffffffffu, sum0, 2);
        sum1 += __shfl_xor_sync(0xffffffffu, sum1, 1);
        sum1 += __shfl_xor_sync(0xffffffffu, sum1, 2);
        lrw0 = lrw0 * a0 + sum0;
        lrw1 = lrw1 * a1 + sum1;

#pragma unroll
        for (int t = 0; t < 8; t++) {
            accO[t][0] *= a0; accO[t][1] *= a0;
            accO[t][2] *= a1; accO[t][3] *= a1;
        }

        // ---- O += P V ----
#pragma unroll
        for (int kk = 0; kk < 4; kk++) {
            uint32_t pah[4], pal[4];
            split_pack(s[2 * kk][0],     s[2 * kk][1],     pah[0], pal[0]);
            split_pack(s[2 * kk][2],     s[2 * kk][3],     pah[1], pal[1]);
            split_pack(s[2 * kk + 1][0], s[2 * kk + 1][1], pah[2], pal[2]);
            split_pack(s[2 * kk + 1][2], s[2 * kk + 1][3], pah[3], pal[3]);
#pragma unroll
            for (int jp = 0; jp < 4; jp++) {
                uint32_t vh[4], vl[4];
                const uint32_t o = v_off + (uint32_t)(kk * 16) * AROW + jp * 32;
                ldmx4t(vh, smb + OFF_VH + o);
                ldmx4t(vl, smb + OFF_VL + o);
                mma_bf16(accO[2 * jp],     pah, vh);
                mma_bf16(accO[2 * jp],     pah, vl);
                mma_bf16(accO[2 * jp],     pal, vh);
                mma_bf16(accO[2 * jp + 1], pah, vh + 2);
                mma_bf16(accO[2 * jp + 1], pah, vl + 2);
                mma_bf16(accO[2 * jp + 1], pal, vh + 2);
            }
        }
    }

    // ---- epilogue ----
    const float inv0 = 1.0f / lrw0;
    const float inv1 = 1.0f / lrw1;
    const int q0 = qbase + w * 16 + (lane >> 2);
    float* o0 = Og + (size_t)(b * SEQ + q0) * D_MODEL + h * HEAD_DIM + 2 * (lane & 3);
    float* o1 = o0 + 8 * D_MODEL;
#pragma unroll
    for (int t = 0; t < 8; t++) {
        *(float2*)(o0 + 8 * t) = make_float2(accO[t][0] * inv0, accO[t][1] * inv0);
        *(float2*)(o1 + 8 * t) = make_float2(accO[t][2] * inv1, accO[t][3] * inv1);
    }
}

// ---------------------------------------------------------------------------
// Launcher — inputs: query key value mask wq bq wk bk wv bv wo bo
// ---------------------------------------------------------------------------
extern "C" void kernel_launch(void* const* d_in, const int* in_sizes, int n_in,
                              void* d_out, int out_size)
{
    const float* query = (const float*)d_in[0];
    const float* key   = (const float*)d_in[1];
    const float* value = (const float*)d_in[2];
    const int*   mask  = (const int*)  d_in[3];
    const float* wq    = (const float*)d_in[4];
    const float* bq    = (const float*)d_in[5];
    const float* wk    = (const float*)d_in[6];
    const float* bk    = (const float*)d_in[7];
    const float* wv    = (const float*)d_in[8];
    const float* bv    = (const float*)d_in[9];
    const float* wo    = (const float*)d_in[10];
    const float* bo    = (const float*)d_in[11];
    float* out = (float*)d_out;

    __nv_bfloat16 *Qh, *Ql, *Kh, *Kl, *Vh, *Vl;
    float *Ab;
    unsigned char* Fl;
    cudaGetSymbolAddress((void**)&Qh, g_Qh);
    cudaGetSymbolAddress((void**)&Ql, g_Ql);
    cudaGetSymbolAddress((void**)&Kh, g_Kh);
    cudaGetSymbolAddress((void**)&Kl, g_Kl);
    cudaGetSymbolAddress((void**)&Vh, g_Vh);
    cudaGetSymbolAddress((void**)&Vl, g_Vl);
    cudaGetSymbolAddress((void**)&Ab, g_att);
    cudaGetSymbolAddress((void**)&Fl, g_mflag);

    cudaFuncSetAttribute(flash_attn_mma_kernel,
                         cudaFuncAttributeMaxDynamicSharedMemorySize, ATTN_SMEM_BYTES);

    dim3 gf(32, 32, BATCH);
    mask_flags_kernel<<<gf, 128>>>(mask, Fl);

    dim3 gg(D_MODEL / 128, M_TOT / 128);   // (8, 32)
    gemm_mma_kernel<true><<<gg, 256>>>(query, wq, bq, nullptr, Qh, Ql);
    gemm_mma_kernel<true><<<gg, 256>>>(key,   wk, bk, nullptr, Kh, Kl);
    gemm_mma_kernel<true><<<gg, 256>>>(value, wv, bv, nullptr, Vh, Vl);

    dim3 ga(SEQ / 64, N_HEADS, BATCH);     // (32, 16, 2)
    flash_attn_mma_kernel<<<ga, 128, ATTN_SMEM_BYTES>>>(
        Qh, Ql, Kh, Kl, Vh, Vl, mask, Fl, Ab);

    gemm_mma_kernel<false><<<gg, 256>>>(Ab, wo, bo, out, nullptr, nullptr);
}

// round 6
// speedup vs baseline: 2.6104x; 1.0741x over previous
#include <cuda_runtime.h>
#include <cuda_bf16.h>
#include <math_constants.h>
#include <cstdint>

#define D_MODEL   1024
#define N_HEADS   16
#define HEAD_DIM  64
#define BATCH     2
#define SEQ       2048
#define M_TOT     (BATCH * SEQ)   // 4096
#define GK        1024

// ---------------------------------------------------------------------------
// Scratch (no cudaMalloc allowed)
// ---------------------------------------------------------------------------
__device__ __nv_bfloat16 g_xq_h[M_TOT * D_MODEL], g_xq_l[M_TOT * D_MODEL];
__device__ __nv_bfloat16 g_xk_h[M_TOT * D_MODEL], g_xk_l[M_TOT * D_MODEL];
__device__ __nv_bfloat16 g_xv_h[M_TOT * D_MODEL], g_xv_l[M_TOT * D_MODEL];
__device__ __nv_bfloat16 g_wq_h[GK * D_MODEL], g_wq_l[GK * D_MODEL];
__device__ __nv_bfloat16 g_wk_h[GK * D_MODEL], g_wk_l[GK * D_MODEL];
__device__ __nv_bfloat16 g_wv_h[GK * D_MODEL], g_wv_l[GK * D_MODEL];
__device__ __nv_bfloat16 g_wo_h[GK * D_MODEL], g_wo_l[GK * D_MODEL];
__device__ __nv_bfloat16 g_Qh[M_TOT * D_MODEL], g_Ql[M_TOT * D_MODEL];
__device__ __nv_bfloat16 g_Kh[M_TOT * D_MODEL], g_Kl[M_TOT * D_MODEL];
__device__ __nv_bfloat16 g_Vh[M_TOT * D_MODEL], g_Vl[M_TOT * D_MODEL];
__device__ __nv_bfloat16 g_Oh[M_TOT * D_MODEL], g_Ol[M_TOT * D_MODEL];
__device__ unsigned char g_mflag[BATCH * 32 * 32];

// ---------------------------------------------------------------------------
// Helpers
// ---------------------------------------------------------------------------
__device__ __forceinline__ uint32_t smem_to_u32(const void* smem_ptr) {
    uint32_t addr;
    asm("{ .reg .u64 tmp; cvta.to.shared.u64 tmp, %1; cvt.u32.u64 %0, tmp; }"
        : "=r"(addr) : "l"(smem_ptr));
    return addr;
}
__device__ __forceinline__ void ldmx4(uint32_t* r, uint32_t addr) {
    asm volatile("ldmatrix.sync.aligned.m8n8.x4.shared.b16 {%0,%1,%2,%3}, [%4];"
        : "=r"(r[0]), "=r"(r[1]), "=r"(r[2]), "=r"(r[3]) : "r"(addr));
}
__device__ __forceinline__ void ldmx4t(uint32_t* r, uint32_t addr) {
    asm volatile("ldmatrix.sync.aligned.m8n8.x4.trans.shared.b16 {%0,%1,%2,%3}, [%4];"
        : "=r"(r[0]), "=r"(r[1]), "=r"(r[2]), "=r"(r[3]) : "r"(addr));
}
__device__ __forceinline__ void ldmx2(uint32_t* r, uint32_t addr) {
    asm volatile("ldmatrix.sync.aligned.m8n8.x2.shared.b16 {%0,%1}, [%2];"
        : "=r"(r[0]), "=r"(r[1]) : "r"(addr));
}
__device__ __forceinline__ void mma_bf16(float* d, const uint32_t* a, const uint32_t* b) {
    asm volatile(
        "mma.sync.aligned.m16n8k16.row.col.f32.bf16.bf16.f32 "
        "{%0,%1,%2,%3}, {%4,%5,%6,%7}, {%8,%9}, {%0,%1,%2,%3};"
        : "+f"(d[0]), "+f"(d[1]), "+f"(d[2]), "+f"(d[3])
        : "r"(a[0]), "r"(a[1]), "r"(a[2]), "r"(a[3]), "r"(b[0]), "r"(b[1]));
}
__device__ __forceinline__ void split_pack(float x, float y, uint32_t& hi, uint32_t& lo) {
    __nv_bfloat162 h = __floats2bfloat162_rn(x, y);
    __nv_bfloat162 l = __floats2bfloat162_rn(x - __low2float(h), y - __high2float(h));
    hi = *reinterpret_cast<uint32_t*>(&h);
    lo = *reinterpret_cast<uint32_t*>(&l);
}
__device__ __forceinline__ void cpa16(uint32_t s, const void* g) {
    asm volatile("cp.async.ca.shared.global [%0], [%1], 16;" :: "r"(s), "l"(g));
}
#define CP_COMMIT() asm volatile("cp.async.commit_group;" ::: "memory")

// ---------------------------------------------------------------------------
// fp32 -> bf16 hi/lo split pre-pass (3-way for activations, 4-way for weights)
// ---------------------------------------------------------------------------
__device__ __forceinline__ void split8_store(const float* s, __nv_bfloat16* h,
                                             __nv_bfloat16* l, int i)
{
    float4 f0 = *(const float4*)(s + i);
    float4 f1 = *(const float4*)(s + i + 4);
    float f[8] = {f0.x, f0.y, f0.z, f0.w, f1.x, f1.y, f1.z, f1.w};
    __nv_bfloat162 hh[4], ll[4];
#pragma unroll
    for (int e = 0; e < 4; e++) {
        hh[e] = __floats2bfloat162_rn(f[2 * e], f[2 * e + 1]);
        ll[e] = __floats2bfloat162_rn(f[2 * e]     - __low2float(hh[e]),
                                      f[2 * e + 1] - __high2float(hh[e]));
    }
    *(uint4*)(h + i) = *(uint4*)hh;
    *(uint4*)(l + i) = *(uint4*)ll;
}

__global__ void split3_kernel(const float* s0, const float* s1, const float* s2,
                              __nv_bfloat16* h0, __nv_bfloat16* l0,
                              __nv_bfloat16* h1, __nv_bfloat16* l1,
                              __nv_bfloat16* h2, __nv_bfloat16* l2)
{
    const float* s; __nv_bfloat16 *h, *l;
    if (blockIdx.z == 0)      { s = s0; h = h0; l = l0; }
    else if (blockIdx.z == 1) { s = s1; h = h1; l = l1; }
    else                      { s = s2; h = h2; l = l2; }
    const int i = (blockIdx.x * blockDim.x + threadIdx.x) * 8;
    split8_store(s, h, l, i);
}

__global__ void split4_kernel(const float* s0, const float* s1, const float* s2, const float* s3,
                              __nv_bfloat16* h0, __nv_bfloat16* l0,
                              __nv_bfloat16* h1, __nv_bfloat16* l1,
                              __nv_bfloat16* h2, __nv_bfloat16* l2,
                              __nv_bfloat16* h3, __nv_bfloat16* l3)
{
    const float* s; __nv_bfloat16 *h, *l;
    if (blockIdx.z == 0)      { s = s0; h = h0; l = l0; }
    else if (blockIdx.z == 1) { s = s1; h = h1; l = l1; }
    else if (blockIdx.z == 2) { s = s2; h = h2; l = l2; }
    else                      { s = s3; h = h3; l = l3; }
    const int i = (blockIdx.x * blockDim.x + threadIdx.x) * 8;
    split8_store(s, h, l, i);
}

// ---------------------------------------------------------------------------
// Pipelined bf16 HMMA GEMM on pre-split operands.
// Y[m][o] = sum_d (Ah+Al)[m][d] * (Bh+Bl)[o][d] + bias[o]  (3-product split)
// CTA 128x128, BK=32, double-buffered cp.async; 8 warps (2x4), warp 64x32.
// ---------------------------------------------------------------------------
#define GSTR 40
#define GROW (GSTR * 2)
#define TILE_B (128 * GSTR * 2)            // 10240 bytes per tile
#define STAGE_B (4 * TILE_B)               // 40960 bytes per stage
#define GEMM_SMEM (2 * STAGE_B)            // 81920 bytes
#define NITER (GK / 32)                    // 32

template<bool OUT_SPLIT>
__global__ __launch_bounds__(256, 2) void gemm_pipe_kernel(
    const __nv_bfloat16* __restrict__ Ah_g, const __nv_bfloat16* __restrict__ Al_g,
    const __nv_bfloat16* __restrict__ Bh_g, const __nv_bfloat16* __restrict__ Bl_g,
    const float* __restrict__ bias, float* __restrict__ Yf,
    __nv_bfloat16* __restrict__ Yh, __nv_bfloat16* __restrict__ Yl)
{
    extern __shared__ char smc[];
    const uint32_t smb = smem_to_u32(smc);

    const int tid    = threadIdx.x;
    const int wid    = tid >> 5;
    const int lane   = tid & 31;
    const int warp_m = wid & 1;
    const int warp_n = wid >> 1;
    const int bm = blockIdx.y * 128;
    const int bn = blockIdx.x * 128;

    float acc[4][4][4];
#pragma unroll
    for (int i = 0; i < 4; i++)
#pragma unroll
        for (int j = 0; j < 4; j++)
#pragma unroll
            for (int k = 0; k < 4; k++) acc[i][j][k] = 0.f;

    // staging map: thread t -> row t>>1, halves segment (t&1)*16 (two 16B chunks)
    const int lrow = tid >> 1;
    const int lseg = (tid & 1) * 16;
    const uint32_t so = (uint32_t)(lrow * GSTR + lseg) * 2;
    const __nv_bfloat16* Ahp = Ah_g + (size_t)(bm + lrow) * GK + lseg;
    const __nv_bfloat16* Alp = Al_g + (size_t)(bm + lrow) * GK + lseg;
    const __nv_bfloat16* Bhp = Bh_g + (size_t)(bn + lrow) * GK + lseg;
    const __nv_bfloat16* Blp = Bl_g + (size_t)(bn + lrow) * GK + lseg;

    const uint32_t a_off = ((uint32_t)(lane & 15) * GSTR + (uint32_t)(lane >> 4) * 8) * 2
                         + (uint32_t)(warp_m * 64) * GROW;
    const uint32_t b_off = ((uint32_t)(lane & 7) * GSTR + (uint32_t)((lane >> 3) & 1) * 8) * 2
                         + (uint32_t)(warp_n * 32) * GROW;

    auto stage = [&](int buf, int kc) {
        const uint32_t base = smb + buf * STAGE_B + so;
        cpa16(base,                 Ahp + kc);
        cpa16(base + 16,            Ahp + kc + 8);
        cpa16(base + TILE_B,        Alp + kc);
        cpa16(base + TILE_B + 16,   Alp + kc + 8);
        cpa16(base + 2 * TILE_B,      Bhp + kc);
        cpa16(base + 2 * TILE_B + 16, Bhp + kc + 8);
        cpa16(base + 3 * TILE_B,      Blp + kc);
        cpa16(base + 3 * TILE_B + 16, Blp + kc + 8);
    };

    stage(0, 0);
    CP_COMMIT();

    for (int it = 0; it < NITER; it++) {
        if (it + 1 < NITER) {
            stage((it + 1) & 1, (it + 1) * 32);
            CP_COMMIT();
            asm volatile("cp.async.wait_group 1;" ::: "memory");
        } else {
            asm volatile("cp.async.wait_group 0;" ::: "memory");
        }
        __syncthreads();

        const uint32_t AhB = smb + (it & 1) * STAGE_B;
        const uint32_t AlB = AhB + TILE_B;
        const uint32_t BhB = AhB + 2 * TILE_B;
        const uint32_t BlB = AhB + 3 * TILE_B;

#pragma unroll
        for (int ks = 0; ks < 2; ks++) {
            const uint32_t ko = (uint32_t)(ks * 32);
            uint32_t ah[4][4], al[4][4];
#pragma unroll
            for (int am = 0; am < 4; am++) {
                const uint32_t o = a_off + (uint32_t)(am * 16) * GROW + ko;
                ldmx4(ah[am], AhB + o);
                ldmx4(al[am], AlB + o);
            }
            uint32_t bh[4][2], bl[4][2];
#pragma unroll
            for (int an = 0; an < 4; an++) {
                const uint32_t o = b_off + (uint32_t)(an * 8) * GROW + ko;
                ldmx2(bh[an], BhB + o);
                ldmx2(bl[an], BlB + o);
            }
#pragma unroll
            for (int am = 0; am < 4; am++)
#pragma unroll
                for (int an = 0; an < 4; an++) {
                    mma_bf16(acc[am][an], ah[am], bh[an]);
                    mma_bf16(acc[am][an], ah[am], bl[an]);
                    mma_bf16(acc[am][an], al[am], bh[an]);
                }
        }
        __syncthreads();
    }

    const int gr = lane >> 2;
    const int gc = (lane & 3) * 2;
#pragma unroll
    for (int am = 0; am < 4; am++) {
#pragma unroll
        for (int an = 0; an < 4; an++) {
            const int row = bm + warp_m * 64 + am * 16 + gr;
            const int col = bn + warp_n * 32 + an * 8 + gc;
            const float b0 = __ldg(&bias[col]);
            const float b1 = __ldg(&bias[col + 1]);
            const float y00 = acc[am][an][0] + b0, y01 = acc[am][an][1] + b1;
            const float y10 = acc[am][an][2] + b0, y11 = acc[am][an][3] + b1;
            if (OUT_SPLIT) {
                uint32_t h0, l0, h1, l1;
                split_pack(y00, y01, h0, l0);
                split_pack(y10, y11, h1, l1);
                *(uint32_t*)&Yh[(size_t)row * D_MODEL + col]       = h0;
                *(uint32_t*)&Yl[(size_t)row * D_MODEL + col]       = l0;
                *(uint32_t*)&Yh[(size_t)(row + 8) * D_MODEL + col] = h1;
                *(uint32_t*)&Yl[(size_t)(row + 8) * D_MODEL + col] = l1;
            } else {
                *(float2*)&Yf[(size_t)row * D_MODEL + col]       = make_float2(y00, y01);
                *(float2*)&Yf[(size_t)(row + 8) * D_MODEL + col] = make_float2(y10, y11);
            }
        }
    }
}

// ---------------------------------------------------------------------------
// Mask tile flag pre-pass
// ---------------------------------------------------------------------------
__global__ __launch_bounds__(128) void mask_flags_kernel(
    const int* __restrict__ mask, unsigned char* __restrict__ flags)
{
    const int kt = blockIdx.x, qt = blockIdx.y, b = blockIdx.z;
    const int tid = threadIdx.x;
    const int row = tid >> 1;
    const int cs  = (tid & 1) * 32;
    const int* p = mask + (size_t)(b * SEQ + qt * 64 + row) * SEQ + kt * 64 + cs;
    int ok = 1;
#pragma unroll
    for (int u = 0; u < 8; u++) {
        int4 v = *(const int4*)(p + 4 * u);
        ok = ok && v.x && v.y && v.z && v.w;
    }
    __shared__ int s_all;
    if (tid == 0) s_all = 1;
    __syncthreads();
    if (!ok) atomicAnd(&s_all, 0);
    __syncthreads();
    if (tid == 0) flags[(b * 32 + qt) * 32 + kt] = (unsigned char)s_all;
}

// ---------------------------------------------------------------------------
// HMMA flash attention on pre-split bf16 Q/K/V; writes pre-split O.
// ---------------------------------------------------------------------------
#define ASTR 72
#define AROW (ASTR * 2)
#define OFF_QH 0
#define OFF_QL (OFF_QH + 64 * AROW)
#define OFF_KH (OFF_QL + 64 * AROW)
#define OFF_KL (OFF_KH + 64 * AROW)
#define OFF_VH (OFF_KL + 64 * AROW)
#define OFF_VL (OFF_VH + 64 * AROW)
#define ATTN_SMEM_BYTES (OFF_VL + 64 * AROW)   // 55296

__global__ __launch_bounds__(128, 4) void flash_attn_mma_kernel(
    const __nv_bfloat16* __restrict__ Qh_g, const __nv_bfloat16* __restrict__ Ql_g,
    const __nv_bfloat16* __restrict__ Kh_g, const __nv_bfloat16* __restrict__ Kl_g,
    const __nv_bfloat16* __restrict__ Vh_g, const __nv_bfloat16* __restrict__ Vl_g,
    const int* __restrict__ mask, const unsigned char* __restrict__ flags,
    __nv_bfloat16* __restrict__ Oh_g, __nv_bfloat16* __restrict__ Ol_g)
{
    extern __shared__ char sm[];
    const uint32_t smb = smem_to_u32(sm);

    const int tid  = threadIdx.x;
    const int w    = tid >> 5;
    const int lane = tid & 31;
    const int qt = blockIdx.x, h = blockIdx.y, b = blockIdx.z;
    const int qbase = qt * 64;
    const float scale = 0.125f;

    const int lrow = tid >> 1;
    const int lseg = (tid & 1) * 32;
    const uint32_t stg = (uint32_t)(lrow * AROW + lseg * 2);

    {
        const size_t go = (size_t)(b * SEQ + qbase + lrow) * D_MODEL + h * HEAD_DIM + lseg;
#pragma unroll
        for (int u = 0; u < 4; u++) {
            cpa16(smb + OFF_QH + stg + 16 * u, Qh_g + go + 8 * u);
            cpa16(smb + OFF_QL + stg + 16 * u, Ql_g + go + 8 * u);
        }
        CP_COMMIT();
        asm volatile("cp.async.wait_group 0;" ::: "memory");
    }
    __syncthreads();

    float accO[8][4];
#pragma unroll
    for (int t = 0; t < 8; t++)
#pragma unroll
        for (int i = 0; i < 4; i++) accO[t][i] = 0.f;
    float mrw0 = -1e30f, mrw1 = -1e30f, lrw0 = 0.f, lrw1 = 0.f;

    const uint32_t q_off = (uint32_t)((w * 16 + (lane & 15)) * AROW + (lane >> 4) * 16);
    const uint32_t k_off = (uint32_t)((((lane >> 4) << 3) + (lane & 7)) * AROW
                                      + ((lane >> 3) & 1) * 16);
    const uint32_t v_off = (uint32_t)(((((lane >> 3) & 1) * 8 + (lane & 7)) * AROW)
                                      + ((lane >> 4) << 4));
    const int mrow = w * 16 + (lane >> 2);
    const int mcol = 2 * (lane & 3);
    const unsigned char* fp = flags + (b * 32 + qt) * 32;

    for (int kt = 0; kt < SEQ; kt += 64) {
        __syncthreads();
        {
            const size_t go = (size_t)(b * SEQ + kt + lrow) * D_MODEL + h * HEAD_DIM + lseg;
#pragma unroll
            for (int u = 0; u < 4; u++) {
                cpa16(smb + OFF_KH + stg + 16 * u, Kh_g + go + 8 * u);
                cpa16(smb + OFF_KL + stg + 16 * u, Kl_g + go + 8 * u);
                cpa16(smb + OFF_VH + stg + 16 * u, Vh_g + go + 8 * u);
                cpa16(smb + OFF_VL + stg + 16 * u, Vl_g + go + 8 * u);
            }
            CP_COMMIT();
            asm volatile("cp.async.wait_group 0;" ::: "memory");
        }
        __syncthreads();

        float s[8][4];
#pragma unroll
        for (int t = 0; t < 8; t++)
#pragma unroll
            for (int i = 0; i < 4; i++) s[t][i] = 0.f;

#pragma unroll
        for (int kk = 0; kk < 4; kk++) {
            uint32_t qh[4], ql[4];
            ldmx4(qh, smb + OFF_QH + q_off + kk * 32);
            ldmx4(ql, smb + OFF_QL + q_off + kk * 32);
#pragma unroll
            for (int p = 0; p < 4; p++) {
                uint32_t bh[4], bl[4];
                const uint32_t o = k_off + (uint32_t)(p * 16) * AROW + kk * 32;
                ldmx4(bh, smb + OFF_KH + o);
                ldmx4(bl, smb + OFF_KL + o);
                mma_bf16(s[2 * p],     qh, bh);
                mma_bf16(s[2 * p],     qh, bl);
                mma_bf16(s[2 * p],     ql, bh);
                mma_bf16(s[2 * p + 1], qh, bh + 2);
                mma_bf16(s[2 * p + 1], qh, bl + 2);
                mma_bf16(s[2 * p + 1], ql, bh + 2);
            }
        }

        if (__ldg(fp + (kt >> 6))) {
#pragma unroll
            for (int t = 0; t < 8; t++) {
                s[t][0] *= scale; s[t][1] *= scale;
                s[t][2] *= scale; s[t][3] *= scale;
            }
        } else {
            const int* mp0 = mask + (size_t)(b * SEQ + qbase + mrow) * SEQ + kt + mcol;
            const int* mp1 = mp0 + 8 * SEQ;
#pragma unroll
            for (int t = 0; t < 8; t++) {
                int2 m0 = *(const int2*)(mp0 + 8 * t);
                int2 m1 = *(const int2*)(mp1 + 8 * t);
                s[t][0] = m0.x ? s[t][0] * scale : -1e30f;
                s[t][1] = m0.y ? s[t][1] * scale : -1e30f;
                s[t][2] = m1.x ? s[t][2] * scale : -1e30f;
                s[t][3] = m1.y ? s[t][3] * scale : -1e30f;
            }
        }

        float mx0 = -1e30f, mx1 = -1e30f;
#pragma unroll
        for (int t = 0; t < 8; t++) {
            mx0 = fmaxf(mx0, fmaxf(s[t][0], s[t][1]));
            mx1 = fmaxf(mx1, fmaxf(s[t][2], s[t][3]));
        }
        mx0 = fmaxf(mx0, __shfl_xor_sync(0xffffffffu, mx0, 1));
        mx0 = fmaxf(mx0, __shfl_xor_sync(0xffffffffu, mx0, 2));
        mx1 = fmaxf(mx1, __shfl_xor_sync(0xffffffffu, mx1, 1));
        mx1 = fmaxf(mx1, __shfl_xor_sync(0xffffffffu, mx1, 2));

        const float mn0 = fmaxf(mrw0, mx0);
        const float mn1 = fmaxf(mrw1, mx1);
        const float a0 = __expf(mrw0 - mn0);
        const float a1 = __expf(mrw1 - mn1);
        mrw0 = mn0; mrw1 = mn1;

        float sum0 = 0.f, sum1 = 0.f;
#pragma unroll
        for (int t = 0; t < 8; t++) {
            s[t][0] = __expf(s[t][0] - mn0);
            s[t][1] = __expf(s[t][1] - mn0);
            s[t][2] = __expf(s[t][2] - mn1);
            s[t][3] = __expf(s[t][3] - mn1);
            sum0 += s[t][0] + s[t][1];
            sum1 += s[t][2] + s[t][3];
        }
        sum0 += __shfl_xor_sync(0xffffffffu, sum0, 1);
        sum0 += __shfl_xor_sync(0xffffffffu, sum0, 2);
        sum1 += __shfl_xor_sync(0xffffffffu, sum1, 1);
        sum1 += __shfl_xor_sync(0xffffffffu, sum1, 2);
        lrw0 = lrw0 * a0 + sum0;
        lrw1 = lrw1 * a1 + sum1;

#pragma unroll
        for (int t = 0; t < 8; t++) {
            accO[t][0] *= a0; accO[t][1] *= a0;
            accO[t][2] *= a1; accO[t][3] *= a1;
        }

#pragma unroll
        for (int kk = 0; kk < 4; kk++) {
            uint32_t pah[4], pal[4];
            split_pack(s[2 * kk][0],     s[2 * kk][1],     pah[0], pal[0]);
            split_pack(s[2 * kk][2],     s[2 * kk][3],     pah[1], pal[1]);
            split_pack(s[2 * kk + 1][0], s[2 * kk + 1][1], pah[2], pal[2]);
            split_pack(s[2 * kk + 1][2], s[2 * kk + 1][3], pah[3], pal[3]);
#pragma unroll
            for (int jp = 0; jp < 4; jp++) {
                uint32_t vh[4], vl[4];
                const uint32_t o = v_off + (uint32_t)(kk * 16) * AROW + jp * 32;
                ldmx4t(vh, smb + OFF_VH + o);
                ldmx4t(vl, smb + OFF_VL + o);
                mma_bf16(accO[2 * jp],     pah, vh);
                mma_bf16(accO[2 * jp],     pah, vl);
                mma_bf16(accO[2 * jp],     pal, vh);
                mma_bf16(accO[2 * jp + 1], pah, vh + 2);
                mma_bf16(accO[2 * jp + 1], pah, vl + 2);
                mma_bf16(accO[2 * jp + 1], pal, vh + 2);
            }
        }
    }

    // ---- epilogue: normalize, split, store bf16 hi/lo ----
    const float inv0 = 1.0f / lrw0;
    const float inv1 = 1.0f / lrw1;
    const int q0 = qbase + w * 16 + (lane >> 2);
    const size_t bo0 = (size_t)(b * SEQ + q0) * D_MODEL + h * HEAD_DIM + 2 * (lane & 3);
    const size_t bo1 = bo0 + 8 * D_MODEL;
#pragma unroll
    for (int t = 0; t < 8; t++) {
        uint32_t h0, l0, h1, l1;
        split_pack(accO[t][0] * inv0, accO[t][1] * inv0, h0, l0);
        split_pack(accO[t][2] * inv1, accO[t][3] * inv1, h1, l1);
        *(uint32_t*)&Oh_g[bo0 + 8 * t] = h0;
        *(uint32_t*)&Ol_g[bo0 + 8 * t] = l0;
        *(uint32_t*)&Oh_g[bo1 + 8 * t] = h1;
        *(uint32_t*)&Ol_g[bo1 + 8 * t] = l1;
    }
}

// ---------------------------------------------------------------------------
// Launcher — inputs: query key value mask wq bq wk bk wv bv wo bo
// ---------------------------------------------------------------------------
extern "C" void kernel_launch(void* const* d_in, const int* in_sizes, int n_in,
                              void* d_out, int out_size)
{
    const float* query = (const float*)d_in[0];
    const float* key   = (const float*)d_in[1];
    const float* value = (const float*)d_in[2];
    const int*   mask  = (const int*)  d_in[3];
    const float* wq    = (const float*)d_in[4];
    const float* bq    = (const float*)d_in[5];
    const float* wk    = (const float*)d_in[6];
    const float* bk    = (const float*)d_in[7];
    const float* wv    = (const float*)d_in[8];
    const float* bv    = (const float*)d_in[9];
    const float* wo    = (const float*)d_in[10];
    const float* bo    = (const float*)d_in[11];
    float* out = (float*)d_out;

    __nv_bfloat16 *xqh, *xql, *xkh, *xkl, *xvh, *xvl;
    __nv_bfloat16 *wqh, *wql, *wkh, *wkl, *wvh, *wvl, *woh, *wol;
    __nv_bfloat16 *Qh, *Ql, *Kh, *Kl, *Vh, *Vl, *Oh, *Ol;
    unsigned char* Fl;
    cudaGetSymbolAddress((void**)&xqh, g_xq_h); cudaGetSymbolAddress((void**)&xql, g_xq_l);
    cudaGetSymbolAddress((void**)&xkh, g_xk_h); cudaGetSymbolAddress((void**)&xkl, g_xk_l);
    cudaGetSymbolAddress((void**)&xvh, g_xv_h); cudaGetSymbolAddress((void**)&xvl, g_xv_l);
    cudaGetSymbolAddress((void**)&wqh, g_wq_h); cudaGetSymbolAddress((void**)&wql, g_wq_l);
    cudaGetSymbolAddress((void**)&wkh, g_wk_h); cudaGetSymbolAddress((void**)&wkl, g_wk_l);
    cudaGetSymbolAddress((void**)&wvh, g_wv_h); cudaGetSymbolAddress((void**)&wvl, g_wv_l);
    cudaGetSymbolAddress((void**)&woh, g_wo_h); cudaGetSymbolAddress((void**)&wol, g_wo_l);
    cudaGetSymbolAddress((void**)&Qh, g_Qh); cudaGetSymbolAddress((void**)&Ql, g_Ql);
    cudaGetSymbolAddress((void**)&Kh, g_Kh); cudaGetSymbolAddress((void**)&Kl, g_Kl);
    cudaGetSymbolAddress((void**)&Vh, g_Vh); cudaGetSymbolAddress((void**)&Vl, g_Vl);
    cudaGetSymbolAddress((void**)&Oh, g_Oh); cudaGetSymbolAddress((void**)&Ol, g_Ol);
    cudaGetSymbolAddress((void**)&Fl, g_mflag);

    cudaFuncSetAttribute(flash_attn_mma_kernel,
                         cudaFuncAttributeMaxDynamicSharedMemorySize, ATTN_SMEM_BYTES);
    cudaFuncSetAttribute(gemm_pipe_kernel<true>,
                         cudaFuncAttributeMaxDynamicSharedMemorySize, GEMM_SMEM);
    cudaFuncSetAttribute(gemm_pipe_kernel<false>,
                         cudaFuncAttributeMaxDynamicSharedMemorySize, GEMM_SMEM);

    // ---- pre-passes ----
    dim3 gf(32, 32, BATCH);
    mask_flags_kernel<<<gf, 128>>>(mask, Fl);
    dim3 g3(M_TOT * D_MODEL / (8 * 256), 1, 3);
    split3_kernel<<<g3, 256>>>(query, key, value, xqh, xql, xkh, xkl, xvh, xvl);
    dim3 g4(GK * D_MODEL / (8 * 256), 1, 4);
    split4_kernel<<<g4, 256>>>(wq, wk, wv, wo, wqh, wql, wkh, wkl, wvh, wvl, woh, wol);

    // ---- QKV projections ----
    dim3 gg(D_MODEL / 128, M_TOT / 128);   // (8, 32)
    gemm_pipe_kernel<true><<<gg, 256, GEMM_SMEM>>>(xqh, xql, wqh, wql, bq, nullptr, Qh, Ql);
    gemm_pipe_kernel<true><<<gg, 256, GEMM_SMEM>>>(xkh, xkl, wkh, wkl, bk, nullptr, Kh, Kl);
    gemm_pipe_kernel<true><<<gg, 256, GEMM_SMEM>>>(xvh, xvl, wvh, wvl, bv, nullptr, Vh, Vl);

    // ---- attention ----
    dim3 ga(SEQ / 64, N_HEADS, BATCH);     // (32, 16, 2)
    flash_attn_mma_kernel<<<ga, 128, ATTN_SMEM_BYTES>>>(
        Qh, Ql, Kh, Kl, Vh, Vl, mask, Fl, Oh, Ol);

    // ---- output projection ----
    gemm_pipe_kernel<false><<<gg, 256, GEMM_SMEM>>>(Oh, Ol, woh, wol, bo, out, nullptr, nullptr);
}

// round 7
// speedup vs baseline: 2.7511x; 1.0539x over previous
#include <cuda_runtime.h>
#include <cuda_bf16.h>
#include <math_constants.h>
#include <cstdint>

#define D_MODEL   1024
#define N_HEADS   16
#define HEAD_DIM  64
#define BATCH     2
#define SEQ       2048
#define M_TOT     (BATCH * SEQ)   // 4096
#define GK        1024

// ---------------------------------------------------------------------------
// Scratch (no cudaMalloc allowed)
// ---------------------------------------------------------------------------
__device__ __nv_bfloat16 g_xq_h[M_TOT * D_MODEL], g_xq_l[M_TOT * D_MODEL];
__device__ __nv_bfloat16 g_xk_h[M_TOT * D_MODEL], g_xk_l[M_TOT * D_MODEL];
__device__ __nv_bfloat16 g_xv_h[M_TOT * D_MODEL], g_xv_l[M_TOT * D_MODEL];
__device__ __nv_bfloat16 g_wq_h[GK * D_MODEL], g_wq_l[GK * D_MODEL];
__device__ __nv_bfloat16 g_wk_h[GK * D_MODEL], g_wk_l[GK * D_MODEL];
__device__ __nv_bfloat16 g_wv_h[GK * D_MODEL], g_wv_l[GK * D_MODEL];
__device__ __nv_bfloat16 g_wo_h[GK * D_MODEL], g_wo_l[GK * D_MODEL];
__device__ __nv_bfloat16 g_Qh[M_TOT * D_MODEL], g_Ql[M_TOT * D_MODEL];
__device__ __nv_bfloat16 g_Kh[M_TOT * D_MODEL], g_Kl[M_TOT * D_MODEL];
__device__ __nv_bfloat16 g_Vh[M_TOT * D_MODEL], g_Vl[M_TOT * D_MODEL];
__device__ __nv_bfloat16 g_Oh[M_TOT * D_MODEL], g_Ol[M_TOT * D_MODEL];
__device__ unsigned char g_mflag[BATCH * 32 * 32];

// ---------------------------------------------------------------------------
// Helpers
// ---------------------------------------------------------------------------
__device__ __forceinline__ uint32_t smem_to_u32(const void* smem_ptr) {
    uint32_t addr;
    asm("{ .reg .u64 tmp; cvta.to.shared.u64 tmp, %1; cvt.u32.u64 %0, tmp; }"
        : "=r"(addr) : "l"(smem_ptr));
    return addr;
}
__device__ __forceinline__ void ldmx4(uint32_t* r, uint32_t addr) {
    asm volatile("ldmatrix.sync.aligned.m8n8.x4.shared.b16 {%0,%1,%2,%3}, [%4];"
        : "=r"(r[0]), "=r"(r[1]), "=r"(r[2]), "=r"(r[3]) : "r"(addr));
}
__device__ __forceinline__ void ldmx4t(uint32_t* r, uint32_t addr) {
    asm volatile("ldmatrix.sync.aligned.m8n8.x4.trans.shared.b16 {%0,%1,%2,%3}, [%4];"
        : "=r"(r[0]), "=r"(r[1]), "=r"(r[2]), "=r"(r[3]) : "r"(addr));
}
__device__ __forceinline__ void mma_bf16(float* d, const uint32_t* a, const uint32_t* b) {
    asm volatile(
        "mma.sync.aligned.m16n8k16.row.col.f32.bf16.bf16.f32 "
        "{%0,%1,%2,%3}, {%4,%5,%6,%7}, {%8,%9}, {%0,%1,%2,%3};"
        : "+f"(d[0]), "+f"(d[1]), "+f"(d[2]), "+f"(d[3])
        : "r"(a[0]), "r"(a[1]), "r"(a[2]), "r"(a[3]), "r"(b[0]), "r"(b[1]));
}
__device__ __forceinline__ void split_pack(float x, float y, uint32_t& hi, uint32_t& lo) {
    __nv_bfloat162 h = __floats2bfloat162_rn(x, y);
    __nv_bfloat162 l = __floats2bfloat162_rn(x - __low2float(h), y - __high2float(h));
    hi = *reinterpret_cast<uint32_t*>(&h);
    lo = *reinterpret_cast<uint32_t*>(&l);
}
__device__ __forceinline__ void cpa16(uint32_t s, const void* g) {
    asm volatile("cp.async.ca.shared.global [%0], [%1], 16;" :: "r"(s), "l"(g));
}
#define CP_COMMIT() asm volatile("cp.async.commit_group;" ::: "memory")

// ---------------------------------------------------------------------------
// fp32 -> bf16 hi/lo split pre-passes
// ---------------------------------------------------------------------------
__device__ __forceinline__ void split8_store(const float* s, __nv_bfloat16* h,
                                             __nv_bfloat16* l, int i)
{
    float4 f0 = *(const float4*)(s + i);
    float4 f1 = *(const float4*)(s + i + 4);
    float f[8] = {f0.x, f0.y, f0.z, f0.w, f1.x, f1.y, f1.z, f1.w};
    __nv_bfloat162 hh[4], ll[4];
#pragma unroll
    for (int e = 0; e < 4; e++) {
        hh[e] = __floats2bfloat162_rn(f[2 * e], f[2 * e + 1]);
        ll[e] = __floats2bfloat162_rn(f[2 * e]     - __low2float(hh[e]),
                                      f[2 * e + 1] - __high2float(hh[e]));
    }
    *(uint4*)(h + i) = *(uint4*)hh;
    *(uint4*)(l + i) = *(uint4*)ll;
}

__global__ void split3_kernel(const float* s0, const float* s1, const float* s2,
                              __nv_bfloat16* h0, __nv_bfloat16* l0,
                              __nv_bfloat16* h1, __nv_bfloat16* l1,
                              __nv_bfloat16* h2, __nv_bfloat16* l2)
{
    const float* s; __nv_bfloat16 *h, *l;
    if (blockIdx.z == 0)      { s = s0; h = h0; l = l0; }
    else if (blockIdx.z == 1) { s = s1; h = h1; l = l1; }
    else                      { s = s2; h = h2; l = l2; }
    const int i = (blockIdx.x * blockDim.x + threadIdx.x) * 8;
    split8_store(s, h, l, i);
}

__global__ void split4_kernel(const float* s0, const float* s1, const float* s2, const float* s3,
                              __nv_bfloat16* h0, __nv_bfloat16* l0,
                              __nv_bfloat16* h1, __nv_bfloat16* l1,
                              __nv_bfloat16* h2, __nv_bfloat16* l2,
                              __nv_bfloat16* h3, __nv_bfloat16* l3)
{
    const float* s; __nv_bfloat16 *h, *l;
    if (blockIdx.z == 0)      { s = s0; h = h0; l = l0; }
    else if (blockIdx.z == 1) { s = s1; h = h1; l = l1; }
    else if (blockIdx.z == 2) { s = s2; h = h2; l = l2; }
    else                      { s = s3; h = h3; l = l3; }
    const int i = (blockIdx.x * blockDim.x + threadIdx.x) * 8;
    split8_store(s, h, l, i);
}

// ---------------------------------------------------------------------------
// Pipelined bf16 HMMA GEMM core (shared by QKV-merged and out-proj kernels).
// CTA 128x128, BK=32, double-buffered cp.async; 8 warps (2x4), warp 64x32.
// B-fragments fetched with ldmx4 (n=16 per LDSM).
// ---------------------------------------------------------------------------
#define GSTR 40
#define GROW (GSTR * 2)
#define TILE_B (128 * GSTR * 2)
#define STAGE_B (4 * TILE_B)
#define GEMM_SMEM (2 * STAGE_B)            // 81920 bytes
#define NITER (GK / 32)

template<bool OUT_SPLIT>
__device__ __forceinline__ void gemm_body(
    const __nv_bfloat16* __restrict__ Ah_g, const __nv_bfloat16* __restrict__ Al_g,
    const __nv_bfloat16* __restrict__ Bh_g, const __nv_bfloat16* __restrict__ Bl_g,
    const float* __restrict__ bias, float* __restrict__ Yf,
    __nv_bfloat16* __restrict__ Yh, __nv_bfloat16* __restrict__ Yl,
    char* smc)
{
    const uint32_t smb = smem_to_u32(smc);
    const int tid    = threadIdx.x;
    const int wid    = tid >> 5;
    const int lane   = tid & 31;
    const int warp_m = wid & 1;
    const int warp_n = wid >> 1;
    const int bm = blockIdx.y * 128;
    const int bn = blockIdx.x * 128;

    float acc[4][4][4];
#pragma unroll
    for (int i = 0; i < 4; i++)
#pragma unroll
        for (int j = 0; j < 4; j++)
#pragma unroll
            for (int k = 0; k < 4; k++) acc[i][j][k] = 0.f;

    const int lrow = tid >> 1;
    const int lseg = (tid & 1) * 16;
    const uint32_t so = (uint32_t)(lrow * GSTR + lseg) * 2;
    const __nv_bfloat16* Ahp = Ah_g + (size_t)(bm + lrow) * GK + lseg;
    const __nv_bfloat16* Alp = Al_g + (size_t)(bm + lrow) * GK + lseg;
    const __nv_bfloat16* Bhp = Bh_g + (size_t)(bn + lrow) * GK + lseg;
    const __nv_bfloat16* Blp = Bl_g + (size_t)(bn + lrow) * GK + lseg;

    const uint32_t a_off = ((uint32_t)(lane & 15) * GSTR + (uint32_t)(lane >> 4) * 8) * 2
                         + (uint32_t)(warp_m * 64) * GROW;
    // x4 B layout: lanes[0:8)=n rows k0, [8:16)=n rows k8, [16:24)=n+8 k0, [24:32)=n+8 k8
    const uint32_t b_off4 = (uint32_t)((lane & 7) + ((lane >> 4) << 3) + warp_n * 32) * GROW
                          + (uint32_t)((lane >> 3) & 1) * 16;

    auto stage = [&](int buf, int kc) {
        const uint32_t base = smb + buf * STAGE_B + so;
        cpa16(base,                   Ahp + kc);
        cpa16(base + 16,              Ahp + kc + 8);
        cpa16(base + TILE_B,          Alp + kc);
        cpa16(base + TILE_B + 16,     Alp + kc + 8);
        cpa16(base + 2 * TILE_B,      Bhp + kc);
        cpa16(base + 2 * TILE_B + 16, Bhp + kc + 8);
        cpa16(base + 3 * TILE_B,      Blp + kc);
        cpa16(base + 3 * TILE_B + 16, Blp + kc + 8);
    };

    stage(0, 0);
    CP_COMMIT();

    for (int it = 0; it < NITER; it++) {
        if (it + 1 < NITER) {
            stage((it + 1) & 1, (it + 1) * 32);
            CP_COMMIT();
            asm volatile("cp.async.wait_group 1;" ::: "memory");
        } else {
            asm volatile("cp.async.wait_group 0;" ::: "memory");
        }
        __syncthreads();

        const uint32_t AhB = smb + (it & 1) * STAGE_B;
        const uint32_t AlB = AhB + TILE_B;
        const uint32_t BhB = AhB + 2 * TILE_B;
        const uint32_t BlB = AhB + 3 * TILE_B;

#pragma unroll
        for (int ks = 0; ks < 2; ks++) {
            const uint32_t ko = (uint32_t)(ks * 32);
            uint32_t ah[4][4], al[4][4];
#pragma unroll
            for (int am = 0; am < 4; am++) {
                const uint32_t o = a_off + (uint32_t)(am * 16) * GROW + ko;
                ldmx4(ah[am], AhB + o);
                ldmx4(al[am], AlB + o);
            }
            uint32_t bh[2][4], bl[2][4];   // [n16-pair][4 regs]
#pragma unroll
            for (int p2 = 0; p2 < 2; p2++) {
                const uint32_t o = b_off4 + (uint32_t)(p2 * 16) * GROW + ko;
                ldmx4(bh[p2], BhB + o);
                ldmx4(bl[p2], BlB + o);
            }
#pragma unroll
            for (int am = 0; am < 4; am++)
#pragma unroll
                for (int an = 0; an < 4; an++) {
                    const uint32_t* bhp = bh[an >> 1] + (an & 1) * 2;
                    const uint32_t* blp = bl[an >> 1] + (an & 1) * 2;
                    mma_bf16(acc[am][an], ah[am], bhp);
                    mma_bf16(acc[am][an], ah[am], blp);
                    mma_bf16(acc[am][an], al[am], bhp);
                }
        }
        __syncthreads();
    }

    const int gr = lane >> 2;
    const int gc = (lane & 3) * 2;
#pragma unroll
    for (int am = 0; am < 4; am++) {
#pragma unroll
        for (int an = 0; an < 4; an++) {
            const int row = bm + warp_m * 64 + am * 16 + gr;
            const int col = bn + warp_n * 32 + an * 8 + gc;
            const float b0 = __ldg(&bias[col]);
            const float b1 = __ldg(&bias[col + 1]);
            const float y00 = acc[am][an][0] + b0, y01 = acc[am][an][1] + b1;
            const float y10 = acc[am][an][2] + b0, y11 = acc[am][an][3] + b1;
            if (OUT_SPLIT) {
                uint32_t h0, l0, h1, l1;
                split_pack(y00, y01, h0, l0);
                split_pack(y10, y11, h1, l1);
                *(uint32_t*)&Yh[(size_t)row * D_MODEL + col]       = h0;
                *(uint32_t*)&Yl[(size_t)row * D_MODEL + col]       = l0;
                *(uint32_t*)&Yh[(size_t)(row + 8) * D_MODEL + col] = h1;
                *(uint32_t*)&Yl[(size_t)(row + 8) * D_MODEL + col] = l1;
            } else {
                *(float2*)&Yf[(size_t)row * D_MODEL + col]       = make_float2(y00, y01);
                *(float2*)&Yf[(size_t)(row + 8) * D_MODEL + col] = make_float2(y10, y11);
            }
        }
    }
}

// Merged QKV: blockIdx.z selects {q,k,v} operand set -> one big launch
__global__ __launch_bounds__(256, 2) void gemm_qkv_kernel(
    const __nv_bfloat16* xqh, const __nv_bfloat16* xql,
    const __nv_bfloat16* xkh, const __nv_bfloat16* xkl,
    const __nv_bfloat16* xvh, const __nv_bfloat16* xvl,
    const __nv_bfloat16* wqh, const __nv_bfloat16* wql,
    const __nv_bfloat16* wkh, const __nv_bfloat16* wkl,
    const __nv_bfloat16* wvh, const __nv_bfloat16* wvl,
    const float* bq, const float* bk, const float* bv,
    __nv_bfloat16* Qh, __nv_bfloat16* Ql,
    __nv_bfloat16* Kh, __nv_bfloat16* Kl,
    __nv_bfloat16* Vh, __nv_bfloat16* Vl)
{
    extern __shared__ char smc[];
    const __nv_bfloat16 *Ah, *Al, *Bh, *Bl;
    const float* bias;
    __nv_bfloat16 *Yh, *Yl;
    if (blockIdx.z == 0) { Ah=xqh; Al=xql; Bh=wqh; Bl=wql; bias=bq; Yh=Qh; Yl=Ql; }
    else if (blockIdx.z == 1) { Ah=xkh; Al=xkl; Bh=wkh; Bl=wkl; bias=bk; Yh=Kh; Yl=Kl; }
    else { Ah=xvh; Al=xvl; Bh=wvh; Bl=wvl; bias=bv; Yh=Vh; Yl=Vl; }
    gemm_body<true>(Ah, Al, Bh, Bl, bias, nullptr, Yh, Yl, smc);
}

__global__ __launch_bounds__(256, 2) void gemm_out_kernel(
    const __nv_bfloat16* Ah, const __nv_bfloat16* Al,
    const __nv_bfloat16* Bh, const __nv_bfloat16* Bl,
    const float* bias, float* Yf)
{
    extern __shared__ char smc[];
    gemm_body<false>(Ah, Al, Bh, Bl, bias, Yf, nullptr, nullptr, smc);
}

// ---------------------------------------------------------------------------
// Mask tile flag pre-pass
// ---------------------------------------------------------------------------
__global__ __launch_bounds__(128) void mask_flags_kernel(
    const int* __restrict__ mask, unsigned char* __restrict__ flags)
{
    const int kt = blockIdx.x, qt = blockIdx.y, b = blockIdx.z;
    const int tid = threadIdx.x;
    const int row = tid >> 1;
    const int cs  = (tid & 1) * 32;
    const int* p = mask + (size_t)(b * SEQ + qt * 64 + row) * SEQ + kt * 64 + cs;
    int ok = 1;
#pragma unroll
    for (int u = 0; u < 8; u++) {
        int4 v = *(const int4*)(p + 4 * u);
        ok = ok && v.x && v.y && v.z && v.w;
    }
    __shared__ int s_all;
    if (tid == 0) s_all = 1;
    __syncthreads();
    if (!ok) atomicAnd(&s_all, 0);
    __syncthreads();
    if (tid == 0) flags[(b * 32 + qt) * 32 + kt] = (unsigned char)s_all;
}

// ---------------------------------------------------------------------------
// HMMA flash attention (unchanged from round 6)
// ---------------------------------------------------------------------------
#define ASTR 72
#define AROW (ASTR * 2)
#define OFF_QH 0
#define OFF_QL (OFF_QH + 64 * AROW)
#define OFF_KH (OFF_QL + 64 * AROW)
#define OFF_KL (OFF_KH + 64 * AROW)
#define OFF_VH (OFF_KL + 64 * AROW)
#define OFF_VL (OFF_VH + 64 * AROW)
#define ATTN_SMEM_BYTES (OFF_VL + 64 * AROW)   // 55296

__global__ __launch_bounds__(128, 4) void flash_attn_mma_kernel(
    const __nv_bfloat16* __restrict__ Qh_g, const __nv_bfloat16* __restrict__ Ql_g,
    const __nv_bfloat16* __restrict__ Kh_g, const __nv_bfloat16* __restrict__ Kl_g,
    const __nv_bfloat16* __restrict__ Vh_g, const __nv_bfloat16* __restrict__ Vl_g,
    const int* __restrict__ mask, const unsigned char* __restrict__ flags,
    __nv_bfloat16* __restrict__ Oh_g, __nv_bfloat16* __restrict__ Ol_g)
{
    extern __shared__ char sm[];
    const uint32_t smb = smem_to_u32(sm);

    const int tid  = threadIdx.x;
    const int w    = tid >> 5;
    const int lane = tid & 31;
    const int qt = blockIdx.x, h = blockIdx.y, b = blockIdx.z;
    const int qbase = qt * 64;
    const float scale = 0.125f;

    const int lrow = tid >> 1;
    const int lseg = (tid & 1) * 32;
    const uint32_t stg = (uint32_t)(lrow * AROW + lseg * 2);

    {
        const size_t go = (size_t)(b * SEQ + qbase + lrow) * D_MODEL + h * HEAD_DIM + lseg;
#pragma unroll
        for (int u = 0; u < 4; u++) {
            cpa16(smb + OFF_QH + stg + 16 * u, Qh_g + go + 8 * u);
            cpa16(smb + OFF_QL + stg + 16 * u, Ql_g + go + 8 * u);
        }
        CP_COMMIT();
        asm volatile("cp.async.wait_group 0;" ::: "memory");
    }
    __syncthreads();

    float accO[8][4];
#pragma unroll
    for (int t = 0; t < 8; t++)
#pragma unroll
        for (int i = 0; i < 4; i++) accO[t][i] = 0.f;
    float mrw0 = -1e30f, mrw1 = -1e30f, lrw0 = 0.f, lrw1 = 0.f;

    const uint32_t q_off = (uint32_t)((w * 16 + (lane & 15)) * AROW + (lane >> 4) * 16);
    const uint32_t k_off = (uint32_t)((((lane >> 4) << 3) + (lane & 7)) * AROW
                                      + ((lane >> 3) & 1) * 16);
    const uint32_t v_off = (uint32_t)(((((lane >> 3) & 1) * 8 + (lane & 7)) * AROW)
                                      + ((lane >> 4) << 4));
    const int mrow = w * 16 + (lane >> 2);
    const int mcol = 2 * (lane & 3);
    const unsigned char* fp = flags + (b * 32 + qt) * 32;

    for (int kt = 0; kt < SEQ; kt += 64) {
        __syncthreads();
        {
            const size_t go = (size_t)(b * SEQ + kt + lrow) * D_MODEL + h * HEAD_DIM + lseg;
#pragma unroll
            for (int u = 0; u < 4; u++) {
                cpa16(smb + OFF_KH + stg + 16 * u, Kh_g + go + 8 * u);
                cpa16(smb + OFF_KL + stg + 16 * u, Kl_g + go + 8 * u);
                cpa16(smb + OFF_VH + stg + 16 * u, Vh_g + go + 8 * u);
                cpa16(smb + OFF_VL + stg + 16 * u, Vl_g + go + 8 * u);
            }
            CP_COMMIT();
            asm volatile("cp.async.wait_group 0;" ::: "memory");
        }
        __syncthreads();

        float s[8][4];
#pragma unroll
        for (int t = 0; t < 8; t++)
#pragma unroll
            for (int i = 0; i < 4; i++) s[t][i] = 0.f;

#pragma unroll
        for (int kk = 0; kk < 4; kk++) {
            uint32_t qh[4], ql[4];
            ldmx4(qh, smb + OFF_QH + q_off + kk * 32);
            ldmx4(ql, smb + OFF_QL + q_off + kk * 32);
#pragma unroll
            for (int p = 0; p < 4; p++) {
                uint32_t bh[4], bl[4];
                const uint32_t o = k_off + (uint32_t)(p * 16) * AROW + kk * 32;
                ldmx4(bh, smb + OFF_KH + o);
                ldmx4(bl, smb + OFF_KL + o);
                mma_bf16(s[2 * p],     qh, bh);
                mma_bf16(s[2 * p],     qh, bl);
                mma_bf16(s[2 * p],     ql, bh);
                mma_bf16(s[2 * p + 1], qh, bh + 2);
                mma_bf16(s[2 * p + 1], qh, bl + 2);
                mma_bf16(s[2 * p + 1], ql, bh + 2);
            }
        }

        if (__ldg(fp + (kt >> 6))) {
#pragma unroll
            for (int t = 0; t < 8; t++) {
                s[t][0] *= scale; s[t][1] *= scale;
                s[t][2] *= scale; s[t][3] *= scale;
            }
        } else {
            const int* mp0 = mask + (size_t)(b * SEQ + qbase + mrow) * SEQ + kt + mcol;
            const int* mp1 = mp0 + 8 * SEQ;
#pragma unroll
            for (int t = 0; t < 8; t++) {
                int2 m0 = *(const int2*)(mp0 + 8 * t);
                int2 m1 = *(const int2*)(mp1 + 8 * t);
                s[t][0] = m0.x ? s[t][0] * scale : -1e30f;
                s[t][1] = m0.y ? s[t][1] * scale : -1e30f;
                s[t][2] = m1.x ? s[t][2] * scale : -1e30f;
                s[t][3] = m1.y ? s[t][3] * scale : -1e30f;
            }
        }

        float mx0 = -1e30f, mx1 = -1e30f;
#pragma unroll
        for (int t = 0; t < 8; t++) {
            mx0 = fmaxf(mx0, fmaxf(s[t][0], s[t][1]));
            mx1 = fmaxf(mx1, fmaxf(s[t][2], s[t][3]));
        }
        mx0 = fmaxf(mx0, __shfl_xor_sync(0xffffffffu, mx0, 1));
        mx0 = fmaxf(mx0, __shfl_xor_sync(0xffffffffu, mx0, 2));
        mx1 = fmaxf(mx1, __shfl_xor_sync(0xffffffffu, mx1, 1));
        mx1 = fmaxf(mx1, __shfl_xor_sync(0xffffffffu, mx1, 2));

        const float mn0 = fmaxf(mrw0, mx0);
        const float mn1 = fmaxf(mrw1, mx1);
        const float a0 = __expf(mrw0 - mn0);
        const float a1 = __expf(mrw1 - mn1);
        mrw0 = mn0; mrw1 = mn1;

        float sum0 = 0.f, sum1 = 0.f;
#pragma unroll
        for (int t = 0; t < 8; t++) {
            s[t][0] = __expf(s[t][0] - mn0);
            s[t][1] = __expf(s[t][1] - mn0);
            s[t][2] = __expf(s[t][2] - mn1);
            s[t][3] = __expf(s[t][3] - mn1);
            sum0 += s[t][0] + s[t][1];
            sum1 += s[t][2] + s[t][3];
        }
        sum0 += __shfl_xor_sync(0xffffffffu, sum0, 1);
        sum0 += __shfl_xor_sync(0xffffffffu, sum0, 2);
        sum1 += __shfl_xor_sync(0xffffffffu, sum1, 1);
        sum1 += __shfl_xor_sync(0xffffffffu, sum1, 2);
        lrw0 = lrw0 * a0 + sum0;
        lrw1 = lrw1 * a1 + sum1;

#pragma unroll
        for (int t = 0; t < 8; t++) {
            accO[t][0] *= a0; accO[t][1] *= a0;
            accO[t][2] *= a1; accO[t][3] *= a1;
        }

#pragma unroll
        for (int kk = 0; kk < 4; kk++) {
            uint32_t pah[4], pal[4];
            split_pack(s[2 * kk][0],     s[2 * kk][1],     pah[0], pal[0]);
            split_pack(s[2 * kk][2],     s[2 * kk][3],     pah[1], pal[1]);
            split_pack(s[2 * kk + 1][0], s[2 * kk + 1][1], pah[2], pal[2]);
            split_pack(s[2 * kk + 1][2], s[2 * kk + 1][3], pah[3], pal[3]);
#pragma unroll
            for (int jp = 0; jp < 4; jp++) {
                uint32_t vh[4], vl[4];
                const uint32_t o = v_off + (uint32_t)(kk * 16) * AROW + jp * 32;
                ldmx4t(vh, smb + OFF_VH + o);
                ldmx4t(vl, smb + OFF_VL + o);
                mma_bf16(accO[2 * jp],     pah, vh);
                mma_bf16(accO[2 * jp],     pah, vl);
                mma_bf16(accO[2 * jp],     pal, vh);
                mma_bf16(accO[2 * jp + 1], pah, vh + 2);
                mma_bf16(accO[2 * jp + 1], pah, vl + 2);
                mma_bf16(accO[2 * jp + 1], pal, vh + 2);
            }
        }
    }

    const float inv0 = 1.0f / lrw0;
    const float inv1 = 1.0f / lrw1;
    const int q0 = qbase + w * 16 + (lane >> 2);
    const size_t bo0 = (size_t)(b * SEQ + q0) * D_MODEL + h * HEAD_DIM + 2 * (lane & 3);
    const size_t bo1 = bo0 + 8 * D_MODEL;
#pragma unroll
    for (int t = 0; t < 8; t++) {
        uint32_t h0, l0, h1, l1;
        split_pack(accO[t][0] * inv0, accO[t][1] * inv0, h0, l0);
        split_pack(accO[t][2] * inv1, accO[t][3] * inv1, h1, l1);
        *(uint32_t*)&Oh_g[bo0 + 8 * t] = h0;
        *(uint32_t*)&Ol_g[bo0 + 8 * t] = l0;
        *(uint32_t*)&Oh_g[bo1 + 8 * t] = h1;
        *(uint32_t*)&Ol_g[bo1 + 8 * t] = l1;
    }
}

// ---------------------------------------------------------------------------
// Launcher — inputs: query key value mask wq bq wk bk wv bv wo bo
// ---------------------------------------------------------------------------
extern "C" void kernel_launch(void* const* d_in, const int* in_sizes, int n_in,
                              void* d_out, int out_size)
{
    const float* query = (const float*)d_in[0];
    const float* key   = (const float*)d_in[1];
    const float* value = (const float*)d_in[2];
    const int*   mask  = (const int*)  d_in[3];
    const float* wq    = (const float*)d_in[4];
    const float* bq    = (const float*)d_in[5];
    const float* wk    = (const float*)d_in[6];
    const float* bk    = (const float*)d_in[7];
    const float* wv    = (const float*)d_in[8];
    const float* bv    = (const float*)d_in[9];
    const float* wo    = (const float*)d_in[10];
    const float* bo    = (const float*)d_in[11];
    float* out = (float*)d_out;

    __nv_bfloat16 *xqh, *xql, *xkh, *xkl, *xvh, *xvl;
    __nv_bfloat16 *wqh, *wql, *wkh, *wkl, *wvh, *wvl, *woh, *wol;
    __nv_bfloat16 *Qh, *Ql, *Kh, *Kl, *Vh, *Vl, *Oh, *Ol;
    unsigned char* Fl;
    cudaGetSymbolAddress((void**)&xqh, g_xq_h); cudaGetSymbolAddress((void**)&xql, g_xq_l);
    cudaGetSymbolAddress((void**)&xkh, g_xk_h); cudaGetSymbolAddress((void**)&xkl, g_xk_l);
    cudaGetSymbolAddress((void**)&xvh, g_xv_h); cudaGetSymbolAddress((void**)&xvl, g_xv_l);
    cudaGetSymbolAddress((void**)&wqh, g_wq_h); cudaGetSymbolAddress((void**)&wql, g_wq_l);
    cudaGetSymbolAddress((void**)&wkh, g_wk_h); cudaGetSymbolAddress((void**)&wkl, g_wk_l);
    cudaGetSymbolAddress((void**)&wvh, g_wv_h); cudaGetSymbolAddress((void**)&wvl, g_wv_l);
    cudaGetSymbolAddress((void**)&woh, g_wo_h); cudaGetSymbolAddress((void**)&wol, g_wo_l);
    cudaGetSymbolAddress((void**)&Qh, g_Qh); cudaGetSymbolAddress((void**)&Ql, g_Ql);
    cudaGetSymbolAddress((void**)&Kh, g_Kh); cudaGetSymbolAddress((void**)&Kl, g_Kl);
    cudaGetSymbolAddress((void**)&Vh, g_Vh); cudaGetSymbolAddress((void**)&Vl, g_Vl);
    cudaGetSymbolAddress((void**)&Oh, g_Oh); cudaGetSymbolAddress((void**)&Ol, g_Ol);
    cudaGetSymbolAddress((void**)&Fl, g_mflag);

    cudaFuncSetAttribute(flash_attn_mma_kernel,
                         cudaFuncAttributeMaxDynamicSharedMemorySize, ATTN_SMEM_BYTES);
    cudaFuncSetAttribute(gemm_qkv_kernel,
                         cudaFuncAttributeMaxDynamicSharedMemorySize, GEMM_SMEM);
    cudaFuncSetAttribute(gemm_out_kernel,
                         cudaFuncAttributeMaxDynamicSharedMemorySize, GEMM_SMEM);

    // ---- pre-passes ----
    dim3 gf(32, 32, BATCH);
    mask_flags_kernel<<<gf, 128>>>(mask, Fl);
    dim3 g3(M_TOT * D_MODEL / (8 * 256), 1, 3);
    split3_kernel<<<g3, 256>>>(query, key, value, xqh, xql, xkh, xkl, xvh, xvl);
    dim3 g4(GK * D_MODEL / (8 * 256), 1, 4);
    split4_kernel<<<g4, 256>>>(wq, wk, wv, wo, wqh, wql, wkh, wkl, wvh, wvl, woh, wol);

    // ---- QKV projections: one merged launch ----
    dim3 gq(D_MODEL / 128, M_TOT / 128, 3);   // (8, 32, 3) = 768 CTAs
    gemm_qkv_kernel<<<gq, 256, GEMM_SMEM>>>(
        xqh, xql, xkh, xkl, xvh, xvl,
        wqh, wql, wkh, wkl, wvh, wvl,
        bq, bk, bv, Qh, Ql, Kh, Kl, Vh, Vl);

    // ---- attention ----
    dim3 ga(SEQ / 64, N_HEADS, BATCH);     // (32, 16, 2)
    flash_attn_mma_kernel<<<ga, 128, ATTN_SMEM_BYTES>>>(
        Qh, Ql, Kh, Kl, Vh, Vl, mask, Fl, Oh, Ol);

    // ---- output projection ----
    dim3 gg(D_MODEL / 128, M_TOT / 128);   // (8, 32)
    gemm_out_kernel<<<gg, 256, GEMM_SMEM>>>(Oh, Ol, woh, wol, bo, out);
}